// round 1
// baseline (speedup 1.0000x reference)
#include <cuda_runtime.h>

#define BATCH   4096
#define ATOMS   64
#define FDIM    124
#define NTYPE   8
#define H1      64
#define H2      16
#define NA      128        // atoms per CTA (2 molecules)
#define NTHREADS 256

// Per-type correction: corr[t] = sum_u c_u - c_t, where c_t = MLP_t(0)
__device__ float d_corr[NTYPE];

__global__ void corr_kernel(const float* __restrict__ b1,
                            const float* __restrict__ W2,
                            const float* __restrict__ b2,
                            const float* __restrict__ W3,
                            const float* __restrict__ b3) {
    __shared__ float c[NTYPE];
    int t = threadIdx.x;
    if (t < NTYPE) {
        float h1v[H1];
        #pragma unroll
        for (int j = 0; j < H1; j++) h1v[j] = fmaxf(b1[t * H1 + j], 0.f);
        float o = b3[t];
        for (int g = 0; g < H2; g++) {
            float v = b2[t * H2 + g];
            #pragma unroll
            for (int h = 0; h < H1; h++) v += h1v[h] * W2[t * H1 * H2 + h * H2 + g];
            o += fmaxf(v, 0.f) * W3[t * H2 + g];
        }
        c[t] = o;
    }
    __syncthreads();
    if (t < NTYPE) {
        float tot = 0.f;
        #pragma unroll
        for (int u = 0; u < NTYPE; u++) tot += c[u];
        d_corr[t] = tot - c[t];
    }
}

struct __align__(16) SmemT {
    float feat[NA][FDIM];       // bucketed by type (permuted)
    float w1[FDIM][H1];         // current type's W1
    float w2t[H2][H1 + 4];      // current type's W2, transposed, padded (bank)
    float hc[16][H1 + 4];       // layer-1 output for current 16-atom chunk
    float h2[16][H2 + 1];       // layer-2 output
    float b1v[H1];
    float b2v[H2];
    float w3v[H2];
    float outv[NA];             // per-atom masked value (original atom order)
    float maskv[NA];
    float molpart[8];
    float b3c;
    float corr;
    float pad_[2];
    int   typ[NA];
    int   perm[NA];             // atom -> bucket slot
    int   rev[NA];              // bucket slot -> atom
    int   cnt[NTYPE];
    int   off[NTYPE];
};

__global__ __launch_bounds__(NTHREADS, 2)
void mol_kernel(const float* __restrict__ x,
                const float* __restrict__ mask,
                const float* __restrict__ W1,
                const float* __restrict__ b1,
                const float* __restrict__ W2,
                const float* __restrict__ b2,
                const float* __restrict__ W3,
                const float* __restrict__ b3,
                float* __restrict__ out) {
    extern __shared__ char smem_raw[];
    SmemT* sm = reinterpret_cast<SmemT*>(smem_raw);
    const int tid = threadIdx.x;
    const int bid = blockIdx.x;
    const size_t gx = (size_t)bid * NA * (FDIM + 1);

    // ---- stage: types, mask ----
    if (tid < NA) {
        int t = (int)x[gx + (size_t)tid * (FDIM + 1)];
        sm->typ[tid] = t;
        sm->maskv[tid] = mask[(size_t)bid * NA + tid];
    }
    __syncthreads();
    // per-type counts (thread t counts; 8 threads, trivial)
    if (tid < NTYPE) {
        int c = 0;
        for (int a = 0; a < NA; a++) c += (sm->typ[a] == tid);
        sm->cnt[tid] = c;
    }
    __syncthreads();
    if (tid == 0) {
        int o = 0;
        for (int t = 0; t < NTYPE; t++) { sm->off[t] = o; o += sm->cnt[t]; }
    }
    __syncthreads();
    // deterministic stable rank -> permutation
    if (tid < NA) {
        int t = sm->typ[tid];
        int r = 0;
        for (int a = 0; a < tid; a++) r += (sm->typ[a] == t);
        int slot = sm->off[t] + r;
        sm->perm[tid] = slot;
        sm->rev[slot] = tid;
    }
    __syncthreads();
    // features -> bucketed SMEM (coalesced global reads)
    for (int idx = tid; idx < NA * FDIM; idx += NTHREADS) {
        int a = idx / FDIM;
        int k = idx - a * FDIM;
        sm->feat[sm->perm[a]][k] = x[gx + (size_t)a * (FDIM + 1) + 1 + k];
    }
    // (covered by the first sync inside the type loop)

    const int hh  = tid & 63;   // layer-1 output column
    const int grp = tid >> 6;   // 4 atom-slots per thread group

    for (int t = 0; t < NTYPE; t++) {
        // ---- stage per-type weights ----
        const float* W1t = W1 + t * FDIM * H1;
        for (int i = tid; i < FDIM * H1; i += NTHREADS)
            (&sm->w1[0][0])[i] = W1t[i];
        for (int i = tid; i < H1 * H2; i += NTHREADS) {
            int h = i >> 4, j = i & 15;
            sm->w2t[j][h] = W2[t * H1 * H2 + i];
        }
        if (tid < H1) sm->b1v[tid] = b1[t * H1 + tid];
        if (tid < H2) { sm->b2v[tid] = b2[t * H2 + tid]; sm->w3v[tid] = W3[t * H2 + tid]; }
        if (tid == 0) { sm->b3c = b3[t]; sm->corr = d_corr[t]; }
        __syncthreads();

        const int start = sm->off[t];
        const int cnt   = sm->cnt[t];
        const int end   = start + cnt;
        const int nchunk = (cnt + 15) >> 4;

        for (int ch = 0; ch < nchunk; ch++) {
            const int base = start + (ch << 4);
            const int s0 = base + (grp << 2);
            // clamp addresses; garbage results for slots >= end are discarded later
            const int sA = min(s0 + 0, NA - 1);
            const int sB = min(s0 + 1, NA - 1);
            const int sC = min(s0 + 2, NA - 1);
            const int sD = min(s0 + 3, NA - 1);
            const float4* fA = (const float4*)sm->feat[sA];
            const float4* fB = (const float4*)sm->feat[sB];
            const float4* fC = (const float4*)sm->feat[sC];
            const float4* fD = (const float4*)sm->feat[sD];
            float acc0 = 0.f, acc1 = 0.f, acc2 = 0.f, acc3 = 0.f;
            #pragma unroll 4
            for (int k4 = 0; k4 < FDIM / 4; k4++) {
                const int k = k4 << 2;
                const float w0 = sm->w1[k + 0][hh];
                const float w1_ = sm->w1[k + 1][hh];
                const float w2_ = sm->w1[k + 2][hh];
                const float w3_ = sm->w1[k + 3][hh];
                float4 a4 = fA[k4];
                acc0 += a4.x * w0 + a4.y * w1_ + a4.z * w2_ + a4.w * w3_;
                float4 b4 = fB[k4];
                acc1 += b4.x * w0 + b4.y * w1_ + b4.z * w2_ + b4.w * w3_;
                float4 c4 = fC[k4];
                acc2 += c4.x * w0 + c4.y * w1_ + c4.z * w2_ + c4.w * w3_;
                float4 d4 = fD[k4];
                acc3 += d4.x * w0 + d4.y * w1_ + d4.z * w2_ + d4.w * w3_;
            }
            const float bb = sm->b1v[hh];
            const int lbase = grp << 2;
            sm->hc[lbase + 0][hh] = fmaxf(acc0 + bb, 0.f);
            sm->hc[lbase + 1][hh] = fmaxf(acc1 + bb, 0.f);
            sm->hc[lbase + 2][hh] = fmaxf(acc2 + bb, 0.f);
            sm->hc[lbase + 3][hh] = fmaxf(acc3 + bb, 0.f);
            __syncthreads();

            // ---- layer 2: 16 atoms x 16 outputs across 256 threads ----
            {
                const int a2 = tid >> 4, j = tid & 15;
                float v = sm->b2v[j];
                #pragma unroll
                for (int h4 = 0; h4 < H1 / 4; h4++) {
                    float4 wv = *(const float4*)&sm->w2t[j][h4 << 2];
                    float4 hv = *(const float4*)&sm->hc[a2][h4 << 2];
                    v += hv.x * wv.x + hv.y * wv.y + hv.z * wv.z + hv.w * wv.w;
                }
                sm->h2[a2][j] = fmaxf(v, 0.f);
            }
            __syncthreads();

            // ---- layer 3 + mask + correction ----
            if (tid < 16) {
                const int slot = base + tid;
                if (slot < end) {
                    float o = sm->b3c;
                    #pragma unroll
                    for (int j = 0; j < H2; j++) o += sm->h2[tid][j] * sm->w3v[j];
                    const int atom = sm->rev[slot];
                    sm->outv[atom] = (o + sm->corr) * sm->maskv[atom];
                }
            }
            __syncthreads();
        }
        __syncthreads();  // safe to overwrite w1/w2t next type
    }

    // ---- deterministic per-molecule reduction ----
    float v = (tid < NA) ? sm->outv[tid] : 0.f;
    #pragma unroll
    for (int o = 16; o > 0; o >>= 1) v += __shfl_down_sync(0xffffffffu, v, o);
    if ((tid & 31) == 0) sm->molpart[tid >> 5] = v;
    __syncthreads();
    if (tid < 2)
        out[(size_t)bid * 2 + tid] = sm->molpart[tid * 2] + sm->molpart[tid * 2 + 1];
}

extern "C" void kernel_launch(void* const* d_in, const int* in_sizes, int n_in,
                              void* d_out, int out_size) {
    const float* x    = (const float*)d_in[0];  // x_padded (4096,64,125)
    const float* mask = (const float*)d_in[1];  // (4096,64)
    const float* W1   = (const float*)d_in[2];  // (8,124,64)
    const float* b1   = (const float*)d_in[3];  // (8,64)
    const float* W2   = (const float*)d_in[4];  // (8,64,16)
    const float* b2   = (const float*)d_in[5];  // (8,16)
    const float* W3   = (const float*)d_in[6];  // (8,16,1)
    const float* b3   = (const float*)d_in[7];  // (8,1)
    float* out = (float*)d_out;                 // (4096,1)

    corr_kernel<<<1, 32>>>(b1, W2, b2, W3, b3);

    const size_t smem = sizeof(SmemT);
    cudaFuncSetAttribute(mol_kernel, cudaFuncAttributeMaxDynamicSharedMemorySize,
                         (int)smem);
    mol_kernel<<<BATCH / 2, NTHREADS, smem>>>(x, mask, W1, b1, W2, b2, W3, b3, out);
}

// round 2
// speedup vs baseline: 1.5213x; 1.5213x over previous
#include <cuda_runtime.h>

#define BATCH    4096
#define ATOMS    64
#define NATOMS   (BATCH * ATOMS)     // 262144
#define FDIM     124
#define XROW     125
#define NTYPE    8
#define H1       64
#define H2       16
#define NA       128                 // atoms per mol-CTA
#define NTHREADS 256
#define LISTCAP  40960               // per-type list capacity (counts ~32768)
#define CHUNKS_PER_TYPE (LISTCAP / NA)   // 320

// ---------------- device globals (static scratch; no allocation) ------------
__device__ float d_corr[NTYPE];
__device__ int   d_cnt[NTYPE];
__device__ int   d_list[NTYPE][LISTCAP];
__device__ float d_peratom[NATOMS];

// ---------------- f32x2 packed helpers (exact fp32 semantics) ---------------
typedef unsigned long long u64;

__device__ __forceinline__ void fma2(u64& d, u64 a, u64 b) {
    asm("fma.rn.f32x2 %0, %1, %2, %0;" : "+l"(d) : "l"(a), "l"(b));
}
__device__ __forceinline__ u64 dup2(float f) {
    u64 r; asm("mov.b64 %0, {%1, %1};" : "=l"(r) : "f"(f)); return r;
}
__device__ __forceinline__ float2 unpack2(u64 v) {
    float2 r; asm("mov.b64 {%0, %1}, %2;" : "=f"(r.x), "=f"(r.y) : "l"(v)); return r;
}

// ---------------- kernel 0: corrections + zero counters ---------------------
__global__ void corr_kernel(const float* __restrict__ b1,
                            const float* __restrict__ W2,
                            const float* __restrict__ b2,
                            const float* __restrict__ W3,
                            const float* __restrict__ b3) {
    __shared__ float c[NTYPE];
    int t = threadIdx.x;
    if (t < NTYPE) d_cnt[t] = 0;
    if (t < NTYPE) {
        float h1v[H1];
        #pragma unroll
        for (int j = 0; j < H1; j++) h1v[j] = fmaxf(b1[t * H1 + j], 0.f);
        float o = b3[t];
        for (int g = 0; g < H2; g++) {
            float v = b2[t * H2 + g];
            #pragma unroll
            for (int h = 0; h < H1; h++) v += h1v[h] * W2[t * H1 * H2 + h * H2 + g];
            o += fmaxf(v, 0.f) * W3[t * H2 + g];
        }
        c[t] = o;
    }
    __syncthreads();
    if (t < NTYPE) {
        float tot = 0.f;
        #pragma unroll
        for (int u = 0; u < NTYPE; u++) tot += c[u];
        d_corr[t] = tot - c[t];
    }
}

// ---------------- kernel 1: classify atoms into per-type lists --------------
__global__ __launch_bounds__(256)
void classify_kernel(const float* __restrict__ x) {
    int atom = blockIdx.x * 256 + threadIdx.x;
    if (atom >= NATOMS) return;
    int t = (int)x[(size_t)atom * XROW];
    int slot = atomicAdd(&d_cnt[t], 1);
    if (slot < LISTCAP) d_list[t][slot] = atom;
}

// ---------------- kernel 2: per-type MLP, 128 atoms per CTA -----------------
// SMEM layout
#define FP   125   // feat pitch (floats)
#define WP   68    // w1 / hc / w2t pitch (floats)

struct __align__(16) Smem2 {
    float feat[NA][FP];          // 64000 B
    float w1s[FDIM][WP];         // 33728 B  (natural [k][h] layout)
    float hc[NA][WP];            // 34816 B  (layer-1 activations)
    float w2t[H2][WP];           //  4352 B  (W2 transposed [j][h])
    float b1s[H1];
    float b2s[H2];
    float w3s[H2];
    float s_mask[NA];
    int   s_atom[NA];
    float b3c, corrv;
};

__global__ __launch_bounds__(NTHREADS, 1)
void mol_kernel(const float* __restrict__ x,
                const float* __restrict__ mask,
                const float* __restrict__ W1,
                const float* __restrict__ b1,
                const float* __restrict__ W2,
                const float* __restrict__ b2,
                const float* __restrict__ W3,
                const float* __restrict__ b3) {
    extern __shared__ char smraw[];
    Smem2* sm = reinterpret_cast<Smem2*>(smraw);
    const int tid  = threadIdx.x;
    const int t    = blockIdx.y;
    const int cnt  = d_cnt[t];
    const int base = blockIdx.x * NA;
    if (base >= cnt) return;
    const int nvalid = min(NA, cnt - base);

    // ---- stage atom ids + masks ----
    if (tid < NA) {
        int idx  = min(base + tid, cnt - 1);
        int a    = d_list[t][idx];
        sm->s_atom[tid] = a;
        sm->s_mask[tid] = mask[a];
    }
    __syncthreads();   // s_atom needed by feature staging below

    // ---- stage features (coalesced per atom row) ----
    {
        const int wid = tid >> 5, lane = tid & 31;
        for (int s = wid; s < NA; s += 8) {
            const float* row = x + (size_t)sm->s_atom[s] * XROW + 1;
            #pragma unroll
            for (int kk = 0; kk < 4; kk++) {
                int k = lane + 32 * kk;
                if (k < FDIM) sm->feat[s][k] = row[k];
            }
        }
    }
    // ---- stage weights ----
    {
        const float* W1t = W1 + (size_t)t * FDIM * H1;
        for (int i = tid; i < FDIM * H1; i += NTHREADS) {
            int k = i >> 6, h = i & 63;
            sm->w1s[k][h] = W1t[i];
        }
        const float* W2t = W2 + (size_t)t * H1 * H2;
        for (int i = tid; i < H1 * H2; i += NTHREADS) {
            int h = i >> 4, j = i & 15;
            sm->w2t[j][h] = W2t[i];
        }
        if (tid < H1) sm->b1s[tid] = b1[t * H1 + tid];
        if (tid < H2) { sm->b2s[tid] = b2[t * H2 + tid]; sm->w3s[tid] = W3[t * H2 + tid]; }
        if (tid == 0) { sm->b3c = b3[t]; sm->corrv = d_corr[t]; }
    }
    __syncthreads();

    // ---- layer 1: thread tile = 4 atoms x 8 cols (as 4 col-pairs, f32x2) ----
    // cols owned: [cA, cA+3] and [cB, cB+3], cA = 4*colgrp, cB = cA + 32.
    const int colgrp = tid & 7;
    const int agrp   = tid >> 3;          // 0..31
    const int s0     = agrp * 4;
    const int cA     = colgrp * 4;
    const int cB     = cA + 32;

    u64 aA0[4], aA1[4], aB0[4], aB1[4];
    {
        u64 bA0 = *(const u64*)&sm->b1s[cA];
        u64 bA1 = *(const u64*)&sm->b1s[cA + 2];
        u64 bB0 = *(const u64*)&sm->b1s[cB];
        u64 bB1 = *(const u64*)&sm->b1s[cB + 2];
        #pragma unroll
        for (int i = 0; i < 4; i++) { aA0[i] = bA0; aA1[i] = bA1; aB0[i] = bB0; aB1[i] = bB1; }
    }
    {
        const float* f0 = sm->feat[s0 + 0];
        const float* f1 = sm->feat[s0 + 1];
        const float* f2 = sm->feat[s0 + 2];
        const float* f3 = sm->feat[s0 + 3];
        #pragma unroll 4
        for (int k = 0; k < FDIM; k++) {
            const float* wr = &sm->w1s[k][0];
            ulonglong2 wA = *(const ulonglong2*)(wr + cA);   // cols cA..cA+3
            ulonglong2 wB = *(const ulonglong2*)(wr + cB);   // cols cB..cB+3
            u64 fd0 = dup2(f0[k]);
            fma2(aA0[0], fd0, wA.x); fma2(aA1[0], fd0, wA.y);
            fma2(aB0[0], fd0, wB.x); fma2(aB1[0], fd0, wB.y);
            u64 fd1 = dup2(f1[k]);
            fma2(aA0[1], fd1, wA.x); fma2(aA1[1], fd1, wA.y);
            fma2(aB0[1], fd1, wB.x); fma2(aB1[1], fd1, wB.y);
            u64 fd2 = dup2(f2[k]);
            fma2(aA0[2], fd2, wA.x); fma2(aA1[2], fd2, wA.y);
            fma2(aB0[2], fd2, wB.x); fma2(aB1[2], fd2, wB.y);
            u64 fd3 = dup2(f3[k]);
            fma2(aA0[3], fd3, wA.x); fma2(aA1[3], fd3, wA.y);
            fma2(aB0[3], fd3, wB.x); fma2(aB1[3], fd3, wB.y);
        }
    }
    // relu + write activations
    #pragma unroll
    for (int i = 0; i < 4; i++) {
        float* hr = &sm->hc[s0 + i][0];
        float2 v;
        v = unpack2(aA0[i]); *(float2*)(hr + cA)     = make_float2(fmaxf(v.x, 0.f), fmaxf(v.y, 0.f));
        v = unpack2(aA1[i]); *(float2*)(hr + cA + 2) = make_float2(fmaxf(v.x, 0.f), fmaxf(v.y, 0.f));
        v = unpack2(aB0[i]); *(float2*)(hr + cB)     = make_float2(fmaxf(v.x, 0.f), fmaxf(v.y, 0.f));
        v = unpack2(aB1[i]); *(float2*)(hr + cB + 2) = make_float2(fmaxf(v.x, 0.f), fmaxf(v.y, 0.f));
    }
    __syncwarp();   // hc rows for this warp's 16 atoms are warp-private

    // ---- layers 2+3: per warp, 16 atoms ----
    {
        const int wid  = tid >> 5, lane = tid & 31;
        const int j    = lane & 15;
        const float w3j = sm->w3s[j];
        const float b2j = sm->b2s[j];
        #pragma unroll 2
        for (int r = 0; r < 8; r++) {
            const int sloc = wid * 16 + 2 * r + (lane >> 4);
            const float* hr = &sm->hc[sloc][0];
            const float* wr = &sm->w2t[j][0];
            float v = b2j;
            #pragma unroll
            for (int h4 = 0; h4 < H1 / 4; h4++) {
                float4 hv = *(const float4*)(hr + h4 * 4);
                float4 wv = *(const float4*)(wr + h4 * 4);
                v += hv.x * wv.x + hv.y * wv.y + hv.z * wv.z + hv.w * wv.w;
            }
            float partial = fmaxf(v, 0.f) * w3j;
            #pragma unroll
            for (int off = 8; off > 0; off >>= 1)
                partial += __shfl_xor_sync(0xffffffffu, partial, off);
            if (j == 0 && sloc < nvalid) {
                float o = (partial + sm->b3c + sm->corrv) * sm->s_mask[sloc];
                d_peratom[sm->s_atom[sloc]] = o;
            }
        }
    }
}

// ---------------- kernel 3: deterministic per-molecule reduction ------------
__global__ __launch_bounds__(256)
void reduce_kernel(float* __restrict__ out) {
    const int wid  = threadIdx.x >> 5;
    const int lane = threadIdx.x & 31;
    const int mol  = blockIdx.x * 8 + wid;
    if (mol >= BATCH) return;
    const float* p = d_peratom + (size_t)mol * ATOMS;
    float v = p[lane] + p[lane + 32];
    #pragma unroll
    for (int off = 16; off > 0; off >>= 1)
        v += __shfl_down_sync(0xffffffffu, v, off);
    if (lane == 0) out[mol] = v;
}

// ---------------- launch ----------------------------------------------------
extern "C" void kernel_launch(void* const* d_in, const int* in_sizes, int n_in,
                              void* d_out, int out_size) {
    const float* x    = (const float*)d_in[0];
    const float* mask = (const float*)d_in[1];
    const float* W1   = (const float*)d_in[2];
    const float* b1   = (const float*)d_in[3];
    const float* W2   = (const float*)d_in[4];
    const float* b2   = (const float*)d_in[5];
    const float* W3   = (const float*)d_in[6];
    const float* b3   = (const float*)d_in[7];
    float* out = (float*)d_out;

    corr_kernel<<<1, 32>>>(b1, W2, b2, W3, b3);
    classify_kernel<<<NATOMS / 256, 256>>>(x);

    static int smem_set = 0;
    if (!smem_set) {
        cudaFuncSetAttribute(mol_kernel, cudaFuncAttributeMaxDynamicSharedMemorySize,
                             (int)sizeof(Smem2));
        smem_set = 1;
    }
    dim3 grid(CHUNKS_PER_TYPE, NTYPE);
    mol_kernel<<<grid, NTHREADS, sizeof(Smem2)>>>(x, mask, W1, b1, W2, b2, W3, b3);

    reduce_kernel<<<BATCH / 8, 256>>>(out);
}

// round 4
// speedup vs baseline: 2.0513x; 1.3484x over previous
#include <cuda_runtime.h>
#include <cuda_bf16.h>

typedef unsigned int       u32;
typedef unsigned long long u64;

#define BATCH    4096
#define ATOMS    64
#define NATOMS   (BATCH * ATOMS)
#define FDIM     124
#define XROW     125
#define NTYPE    8
#define H1       64
#define H2       16
#define NA       128                 // atoms per CTA (M)
#define NTHREADS 256
#define LISTCAP  40960
#define CHUNKS_PER_TYPE (LISTCAP / NA)

#define PITCH    272                 // bytes per 136-bf16 row (conflict-free ldmatrix)

// ---------------- SMEM layout (bytes) ---------------------------------------
#define OFF_AHI  0                         // A hi  128 x PITCH = 34816
#define OFF_ALO  (OFF_AHI + NA * PITCH)    // A lo            34816
#define OFF_BHI  (OFF_ALO + NA * PITCH)    // B hi  64 x PITCH = 17408
#define OFF_BLO  (OFF_BHI + H1 * PITCH)    // B lo            17408
#define OFF_W2   (OFF_BLO + H1 * PITCH)    // w2t [16][68] f32 = 4352
#define OFF_B1   (OFF_W2 + 4352)           // 256
#define OFF_B2   (OFF_B1 + 256)            // 64
#define OFF_W3   (OFF_B2 + 64)             // 64
#define OFF_MASK (OFF_W3 + 64)             // 512
#define OFF_ATOM (OFF_MASK + 512)          // 512
#define OFF_MISC (OFF_ATOM + 512)          // 16
#define SMEM_TOTAL (OFF_MISC + 16)         // ~110 KB -> 2 CTAs/SM

// ---------------- device globals (static scratch) ---------------------------
__device__ float d_corr[NTYPE];
__device__ int   d_cnt[NTYPE];
__device__ int   d_list[NTYPE][LISTCAP];
__device__ float d_peratom[NATOMS];
__device__ u32   d_w1hi[NTYPE][H1 * 64];   // [t][n][kpair] packed bf16x2, k padded to 128
__device__ u32   d_w1lo[NTYPE][H1 * 64];

// ---------------- helpers ----------------------------------------------------
__device__ __forceinline__ u32 smem_u32(const void* p) {
    u32 a;
    asm("{ .reg .u64 t; cvta.to.shared.u64 t, %1; cvt.u32.u64 %0, t; }"
        : "=r"(a) : "l"(p));
    return a;
}
// packed: high half = b (odd elem), low half = a (even elem)
__device__ __forceinline__ u32 cvt2bf(float hi_elem, float lo_elem) {
    u32 r;
    asm("cvt.rn.bf16x2.f32 %0, %1, %2;" : "=r"(r) : "f"(hi_elem), "f"(lo_elem));
    return r;
}
__device__ __forceinline__ void ldmx4(u32* r, u32 addr) {
    asm volatile("ldmatrix.sync.aligned.m8n8.x4.shared.b16 {%0,%1,%2,%3}, [%4];"
                 : "=r"(r[0]), "=r"(r[1]), "=r"(r[2]), "=r"(r[3]) : "r"(addr));
}
__device__ __forceinline__ void mma_bf16(float* d, const u32* a, u32 b0, u32 b1) {
    asm volatile(
        "mma.sync.aligned.m16n8k16.row.col.f32.bf16.bf16.f32 "
        "{%0,%1,%2,%3}, {%4,%5,%6,%7}, {%8,%9}, {%0,%1,%2,%3};"
        : "+f"(d[0]), "+f"(d[1]), "+f"(d[2]), "+f"(d[3])
        : "r"(a[0]), "r"(a[1]), "r"(a[2]), "r"(a[3]), "r"(b0), "r"(b1));
}

// ---------------- kernel 0: corrections + zero counters ---------------------
__global__ void corr_kernel(const float* __restrict__ b1,
                            const float* __restrict__ W2,
                            const float* __restrict__ b2,
                            const float* __restrict__ W3,
                            const float* __restrict__ b3) {
    __shared__ float c[NTYPE];
    int t = threadIdx.x;
    if (t < NTYPE) d_cnt[t] = 0;
    if (t < NTYPE) {
        float h1v[H1];
        #pragma unroll
        for (int j = 0; j < H1; j++) h1v[j] = fmaxf(b1[t * H1 + j], 0.f);
        float o = b3[t];
        for (int g = 0; g < H2; g++) {
            float v = b2[t * H2 + g];
            #pragma unroll
            for (int h = 0; h < H1; h++) v += h1v[h] * W2[t * H1 * H2 + h * H2 + g];
            o += fmaxf(v, 0.f) * W3[t * H2 + g];
        }
        c[t] = o;
    }
    __syncthreads();
    if (t < NTYPE) {
        float tot = 0.f;
        #pragma unroll
        for (int u = 0; u < NTYPE; u++) tot += c[u];
        d_corr[t] = tot - c[t];
    }
}

// ---------------- kernel 0b: pre-split W1 into bf16 hi/lo (transposed) -------
__global__ __launch_bounds__(256)
void wsplit_kernel(const float* __restrict__ W1) {
    const int t = blockIdx.x;
    for (int i = threadIdx.x; i < H1 * 64; i += 256) {
        int n = i >> 6, p = i & 63;
        u32 hiw = 0, low = 0;
        if (p < FDIM / 2) {
            float va = W1[(size_t)t * FDIM * H1 + (2 * p) * H1 + n];
            float vb = W1[(size_t)t * FDIM * H1 + (2 * p + 1) * H1 + n];
            hiw = cvt2bf(vb, va);
            float ha = __uint_as_float(hiw << 16);
            float hb = __uint_as_float(hiw & 0xFFFF0000u);
            low = cvt2bf(vb - hb, va - ha);
        }
        d_w1hi[t][i] = hiw;
        d_w1lo[t][i] = low;
    }
}

// ---------------- kernel 1: classify ----------------------------------------
__global__ __launch_bounds__(256)
void classify_kernel(const float* __restrict__ x) {
    int atom = blockIdx.x * 256 + threadIdx.x;
    if (atom >= NATOMS) return;
    int t = (int)x[(size_t)atom * XROW];
    int slot = atomicAdd(&d_cnt[t], 1);
    if (slot < LISTCAP) d_list[t][slot] = atom;
}

// ---------------- kernel 2: mma.sync MLP, 128 atoms per CTA -----------------
__global__ __launch_bounds__(NTHREADS, 2)
void mol_kernel(const float* __restrict__ x,
                const float* __restrict__ mask,
                const float* __restrict__ W2,
                const float* __restrict__ b1,
                const float* __restrict__ b2,
                const float* __restrict__ W3,
                const float* __restrict__ b3) {
    extern __shared__ char sm[];
    const int tid = threadIdx.x, wid = tid >> 5, lane = tid & 31;
    const int t = blockIdx.y;
    const int cnt = d_cnt[t];
    const int base = blockIdx.x * NA;
    if (base >= cnt) return;
    const int nvalid = min(NA, cnt - base);
    const u32 smb = smem_u32(sm);

    int*   s_atom = (int*)(sm + OFF_ATOM);
    float* s_mask = (float*)(sm + OFF_MASK);
    float* b1s    = (float*)(sm + OFF_B1);
    float* b2s    = (float*)(sm + OFF_B2);
    float* w3s    = (float*)(sm + OFF_W3);
    float* w2t    = (float*)(sm + OFF_W2);   // [16][68]

    // ---- stage atom ids + masks ----
    if (tid < NA) {
        int idx = min(base + tid, cnt - 1);
        int a = d_list[t][idx];
        s_atom[tid] = a;
        s_mask[tid] = mask[a];
    }
    // ---- small weights ----
    for (int i = tid; i < H1 * H2; i += NTHREADS) {
        int h = i >> 4, j = i & 15;
        w2t[j * 68 + h] = W2[(size_t)t * H1 * H2 + i];
    }
    if (tid < H1) b1s[tid] = b1[t * H1 + tid];
    if (tid < H2) { b2s[tid] = b2[t * H2 + tid]; w3s[tid] = W3[t * H2 + tid]; }
    if (tid == 0) {
        ((float*)(sm + OFF_MISC))[0] = b3[t];
        ((float*)(sm + OFF_MISC))[1] = d_corr[t];
    }
    // ---- B tiles: copy pre-split W1 (u32 words; pad pairs already zero) ----
    {
        const u32* whi = d_w1hi[t];
        const u32* wlo = d_w1lo[t];
        for (int i = tid; i < H1 * 64; i += NTHREADS) {
            int n = i >> 6, p = i & 63;
            u32 o = (u32)(n * PITCH + 4 * p);
            *(u32*)(sm + OFF_BHI + o) = whi[i];
            *(u32*)(sm + OFF_BLO + o) = wlo[i];
        }
    }
    // ---- A pad (k pairs 62,63 -> zero) ----
    for (int s = tid; s < NA; s += NTHREADS) {
        *(u64*)(sm + OFF_AHI + s * PITCH + 248) = 0ull;
        *(u64*)(sm + OFF_ALO + s * PITCH + 248) = 0ull;
    }
    __syncthreads();   // s_atom visible before feature gather

    // ---- A tiles: gather features, split to bf16 hi/lo ----
    for (int s = wid; s < NA; s += 8) {
        const float* row = x + (size_t)s_atom[s] * XROW + 1;
        const u32 abase = (u32)(s * PITCH);
        for (int p = lane; p < FDIM / 2; p += 32) {
            float v0 = row[2 * p], v1 = row[2 * p + 1];
            u32 hiw = cvt2bf(v1, v0);
            float h0 = __uint_as_float(hiw << 16);
            float h1 = __uint_as_float(hiw & 0xFFFF0000u);
            u32 low = cvt2bf(v1 - h1, v0 - h0);
            *(u32*)(sm + OFF_AHI + abase + 4 * p) = hiw;
            *(u32*)(sm + OFF_ALO + abase + 4 * p) = low;
        }
    }
    __syncthreads();

    // ---- layer 1: per-warp 16x64 tile, split-bf16 mma.sync ----
    float acc[32];
    #pragma unroll
    for (int i = 0; i < 32; i++) acc[i] = 0.f;

    const int wg16 = wid * 16;
    const u32 aoff = (u32)((wg16 + (lane & 15)) * PITCH + ((lane >> 4) * 16));
    const int b_n  = (lane & 7) + ((lane >> 4) << 3);
    const u32 boff = (u32)(b_n * PITCH + (((lane >> 3) & 1) * 16));

    #pragma unroll
    for (int kc = 0; kc < 8; kc++) {
        const u32 kbyte = kc * 32;
        u32 aH[4], aL[4];
        ldmx4(aH, smb + OFF_AHI + aoff + kbyte);
        ldmx4(aL, smb + OFF_ALO + aoff + kbyte);
        #pragma unroll
        for (int q = 0; q < 4; q++) {           // q covers n-tiles 2q, 2q+1
            u32 bH[4], bL[4];
            const u32 bo = boff + (u32)(q * 16 * PITCH) + kbyte;
            ldmx4(bH, smb + OFF_BHI + bo);
            ldmx4(bL, smb + OFF_BLO + bo);
            float* d0 = acc + (2 * q) * 4;
            float* d1 = acc + (2 * q + 1) * 4;
            mma_bf16(d0, aH, bH[0], bH[1]);
            mma_bf16(d1, aH, bH[2], bH[3]);
            mma_bf16(d0, aH, bL[0], bL[1]);
            mma_bf16(d1, aH, bL[2], bL[3]);
            mma_bf16(d0, aL, bH[0], bH[1]);
            mma_bf16(d1, aL, bH[2], bH[3]);
        }
    }

    // ---- bias + relu, write h1 into own A_hi rows (f32, pitch 272) ----
    {
        const int r0 = wg16 + (lane >> 2);
        const int c0 = (lane & 3) * 2;
        #pragma unroll
        for (int nt = 0; nt < 8; nt++) {
            const int col = nt * 8 + c0;
            const float bb0 = b1s[col], bb1 = b1s[col + 1];
            float2 v;
            v.x = fmaxf(acc[nt * 4 + 0] + bb0, 0.f);
            v.y = fmaxf(acc[nt * 4 + 1] + bb1, 0.f);
            *(float2*)(sm + OFF_AHI + r0 * PITCH + col * 4) = v;
            v.x = fmaxf(acc[nt * 4 + 2] + bb0, 0.f);
            v.y = fmaxf(acc[nt * 4 + 3] + bb1, 0.f);
            *(float2*)(sm + OFF_AHI + (r0 + 8) * PITCH + col * 4) = v;
        }
    }
    __syncwarp();

    // ---- layers 2+3 (per warp, its 16 atoms) ----
    {
        const int j = lane & 15;
        const float w3j = w3s[j];
        const float b2j = b2s[j];
        const float b3c = ((const float*)(sm + OFF_MISC))[0];
        const float cv  = ((const float*)(sm + OFF_MISC))[1];
        #pragma unroll 2
        for (int r = 0; r < 8; r++) {
            const int sloc = wg16 + 2 * r + (lane >> 4);
            const float* hr = (const float*)(sm + OFF_AHI + sloc * PITCH);
            const float* wr = &w2t[j * 68];
            float v = b2j;
            #pragma unroll
            for (int h4 = 0; h4 < H1 / 4; h4++) {
                float4 hv = *(const float4*)(hr + h4 * 4);
                float4 wv = *(const float4*)(wr + h4 * 4);
                v += hv.x * wv.x + hv.y * wv.y + hv.z * wv.z + hv.w * wv.w;
            }
            float partial = fmaxf(v, 0.f) * w3j;
            #pragma unroll
            for (int off = 8; off > 0; off >>= 1)
                partial += __shfl_xor_sync(0xffffffffu, partial, off);
            if (j == 0 && sloc < nvalid) {
                d_peratom[s_atom[sloc]] = (partial + b3c + cv) * s_mask[sloc];
            }
        }
    }
}

// ---------------- kernel 3: per-molecule reduction --------------------------
__global__ __launch_bounds__(256)
void reduce_kernel(float* __restrict__ out) {
    const int wid = threadIdx.x >> 5;
    const int lane = threadIdx.x & 31;
    const int mol = blockIdx.x * 8 + wid;
    if (mol >= BATCH) return;
    const float* p = d_peratom + (size_t)mol * ATOMS;
    float v = p[lane] + p[lane + 32];
    #pragma unroll
    for (int off = 16; off > 0; off >>= 1)
        v += __shfl_down_sync(0xffffffffu, v, off);
    if (lane == 0) out[mol] = v;
}

// ---------------- launch ----------------------------------------------------
extern "C" void kernel_launch(void* const* d_in, const int* in_sizes, int n_in,
                              void* d_out, int out_size) {
    const float* x    = (const float*)d_in[0];
    const float* mask = (const float*)d_in[1];
    const float* W1   = (const float*)d_in[2];
    const float* b1   = (const float*)d_in[3];
    const float* W2   = (const float*)d_in[4];
    const float* b2   = (const float*)d_in[5];
    const float* W3   = (const float*)d_in[6];
    const float* b3   = (const float*)d_in[7];
    float* out = (float*)d_out;

    corr_kernel<<<1, 32>>>(b1, W2, b2, W3, b3);
    wsplit_kernel<<<NTYPE, 256>>>(W1);
    classify_kernel<<<NATOMS / 256, 256>>>(x);

    static int smem_set = 0;
    if (!smem_set) {
        cudaFuncSetAttribute(mol_kernel, cudaFuncAttributeMaxDynamicSharedMemorySize,
                             SMEM_TOTAL);
        smem_set = 1;
    }
    dim3 grid(CHUNKS_PER_TYPE, NTYPE);
    mol_kernel<<<grid, NTHREADS, SMEM_TOTAL>>>(x, mask, W2, b1, b2, W3, b3);

    reduce_kernel<<<BATCH / 8, 256>>>(out);
}

// round 5
// speedup vs baseline: 2.9765x; 1.4510x over previous
#include <cuda_runtime.h>
#include <cuda_bf16.h>

typedef unsigned int       u32;
typedef unsigned long long u64;

#define BATCH    4096
#define ATOMS    64
#define NATOMS   (BATCH * ATOMS)
#define FDIM     124
#define XROW     125
#define NTYPE    8
#define H1       64
#define H2       16
#define NA       64                  // atoms per CTA (M)
#define NTHREADS 256
#define LISTCAP  40960
#define CHUNKS_PER_TYPE (LISTCAP / NA)   // 640

#define PITCH    272                 // bytes per row (conflict-free ldmatrix)

// ---------------- SMEM layout (bytes) ---------------------------------------
#define OFF_AHI  0                         // 64 x 272 = 17408
#define OFF_ALO  17408
#define OFF_BHI  34816                     // 64 x 272
#define OFF_BLO  52224
#define OFF_W2   69632                     // [16][68] f32 = 4352
#define OFF_B1   73984                     // 256
#define OFF_B2   74240                     // 64
#define OFF_W3   74304                     // 64
#define OFF_MASK 74368                     // 256
#define OFF_ATOM 74624                     // 256
#define OFF_MISC 74880                     // 16
#define SMEM_TOTAL 74896                   // -> 3 CTAs/SM

// ---------------- device globals (static scratch) ---------------------------
__device__ float d_corr[NTYPE];
__device__ int   d_cnt[NTYPE];
__device__ int   d_list[NTYPE][LISTCAP];
__device__ float d_peratom[NATOMS];
__device__ u32   d_w1hi[NTYPE][H1 * 64];   // [t][n][kpair] bf16x2, k padded to 128
__device__ u32   d_w1lo[NTYPE][H1 * 64];

// ---------------- helpers ----------------------------------------------------
__device__ __forceinline__ u32 smem_u32(const void* p) {
    u32 a;
    asm("{ .reg .u64 t; cvta.to.shared.u64 t, %1; cvt.u32.u64 %0, t; }"
        : "=r"(a) : "l"(p));
    return a;
}
__device__ __forceinline__ u32 cvt2bf(float hi_elem, float lo_elem) {
    u32 r;
    asm("cvt.rn.bf16x2.f32 %0, %1, %2;" : "=r"(r) : "f"(hi_elem), "f"(lo_elem));
    return r;
}
__device__ __forceinline__ void ldmx4(u32* r, u32 addr) {
    asm volatile("ldmatrix.sync.aligned.m8n8.x4.shared.b16 {%0,%1,%2,%3}, [%4];"
                 : "=r"(r[0]), "=r"(r[1]), "=r"(r[2]), "=r"(r[3]) : "r"(addr));
}
__device__ __forceinline__ void mma_bf16(float* d, const u32* a, u32 b0, u32 b1) {
    asm volatile(
        "mma.sync.aligned.m16n8k16.row.col.f32.bf16.bf16.f32 "
        "{%0,%1,%2,%3}, {%4,%5,%6,%7}, {%8,%9}, {%0,%1,%2,%3};"
        : "+f"(d[0]), "+f"(d[1]), "+f"(d[2]), "+f"(d[3])
        : "r"(a[0]), "r"(a[1]), "r"(a[2]), "r"(a[3]), "r"(b0), "r"(b1));
}
__device__ __forceinline__ u64 pack64(u32 lo, u32 hi) {
    u64 r; asm("mov.b64 %0, {%1, %2};" : "=l"(r) : "r"(lo), "r"(hi)); return r;
}

// ---------------- kernel 0: W1 split + corrections + zero counters ----------
__global__ __launch_bounds__(256)
void prep_kernel(const float* __restrict__ W1,
                 const float* __restrict__ b1,
                 const float* __restrict__ W2,
                 const float* __restrict__ b2,
                 const float* __restrict__ W3,
                 const float* __restrict__ b3) {
    const int t = blockIdx.x;
    // ---- split W1[t] into bf16 hi/lo (transposed [n][kpair], pad to 64) ----
    for (int i = threadIdx.x; i < H1 * 64; i += 256) {
        int n = i >> 6, p = i & 63;
        u32 hiw = 0, low = 0;
        if (p < FDIM / 2) {
            float va = W1[(size_t)t * FDIM * H1 + (2 * p) * H1 + n];
            float vb = W1[(size_t)t * FDIM * H1 + (2 * p + 1) * H1 + n];
            hiw = cvt2bf(vb, va);
            float ha = __uint_as_float(hiw << 16);
            float hb = __uint_as_float(hiw & 0xFFFF0000u);
            low = cvt2bf(vb - hb, va - ha);
        }
        d_w1hi[t][i] = hiw;
        d_w1lo[t][i] = low;
    }
    // ---- block 0: zero counters + per-type corrections ----
    if (blockIdx.x == 0) {
        __shared__ float c[NTYPE];
        int u = threadIdx.x;
        if (u < NTYPE) {
            d_cnt[u] = 0;
            float h1v[H1];
            #pragma unroll
            for (int j = 0; j < H1; j++) h1v[j] = fmaxf(b1[u * H1 + j], 0.f);
            float o = b3[u];
            for (int g = 0; g < H2; g++) {
                float v = b2[u * H2 + g];
                #pragma unroll
                for (int h = 0; h < H1; h++) v += h1v[h] * W2[u * H1 * H2 + h * H2 + g];
                o += fmaxf(v, 0.f) * W3[u * H2 + g];
            }
            c[u] = o;
        }
        __syncthreads();
        if (u < NTYPE) {
            float tot = 0.f;
            #pragma unroll
            for (int v = 0; v < NTYPE; v++) tot += c[v];
            d_corr[u] = tot - c[u];
        }
    }
}

// ---------------- kernel 1: classify (smem-aggregated atomics) --------------
#define CLS_ATOMS 1024
__global__ __launch_bounds__(256)
void classify_kernel(const float* __restrict__ x) {
    __shared__ int s_cnt[NTYPE];
    __shared__ int s_base[NTYPE];
    const int tid = threadIdx.x;
    if (tid < NTYPE) s_cnt[tid] = 0;
    __syncthreads();
    const int a0 = blockIdx.x * CLS_ATOMS + tid * 4;
    int ty[4], rk[4];
    float tf0 = x[(size_t)(a0 + 0) * XROW];
    float tf1 = x[(size_t)(a0 + 1) * XROW];
    float tf2 = x[(size_t)(a0 + 2) * XROW];
    float tf3 = x[(size_t)(a0 + 3) * XROW];
    ty[0] = (int)tf0; ty[1] = (int)tf1; ty[2] = (int)tf2; ty[3] = (int)tf3;
    #pragma unroll
    for (int i = 0; i < 4; i++) rk[i] = atomicAdd(&s_cnt[ty[i]], 1);
    __syncthreads();
    if (tid < NTYPE) s_base[tid] = atomicAdd(&d_cnt[tid], s_cnt[tid]);
    __syncthreads();
    #pragma unroll
    for (int i = 0; i < 4; i++)
        d_list[ty[i]][s_base[ty[i]] + rk[i]] = a0 + i;
}

// ---------------- kernel 2: mma.sync MLP, 64 atoms per CTA ------------------
__global__ __launch_bounds__(NTHREADS, 3)
void mol_kernel(const float* __restrict__ x,
                const float* __restrict__ mask,
                const float* __restrict__ W2,
                const float* __restrict__ b1,
                const float* __restrict__ b2,
                const float* __restrict__ W3,
                const float* __restrict__ b3) {
    extern __shared__ char sm[];
    const int tid = threadIdx.x, wid = tid >> 5, lane = tid & 31;
    const int t = blockIdx.y;
    const int cnt = d_cnt[t];
    const int base = blockIdx.x * NA;
    if (base >= cnt) return;
    const int nvalid = min(NA, cnt - base);
    const u32 smb = smem_u32(sm);

    int*   s_atom = (int*)(sm + OFF_ATOM);
    float* s_mask = (float*)(sm + OFF_MASK);
    float* b1s    = (float*)(sm + OFF_B1);
    float* b2s    = (float*)(sm + OFF_B2);
    float* w3s    = (float*)(sm + OFF_W3);
    float* w2t    = (float*)(sm + OFF_W2);   // [16][68]

    // ---- stage atom ids + masks + small weights ----
    if (tid < NA) {
        int idx = min(base + tid, cnt - 1);
        int a = d_list[t][idx];
        s_atom[tid] = a;
        s_mask[tid] = mask[a];
    }
    for (int i = tid; i < H1 * H2; i += NTHREADS) {
        int h = i >> 4, j = i & 15;
        w2t[j * 68 + h] = W2[(size_t)t * H1 * H2 + i];
    }
    if (tid < H1) b1s[tid] = b1[t * H1 + tid];
    if (tid < H2) { b2s[tid] = b2[t * H2 + tid]; w3s[tid] = W3[t * H2 + tid]; }
    if (tid == 0) {
        ((float*)(sm + OFF_MISC))[0] = b3[t];
        ((float*)(sm + OFF_MISC))[1] = d_corr[t];
    }
    // ---- B tiles: copy pre-split W1 ----
    {
        const u32* whi = d_w1hi[t];
        const u32* wlo = d_w1lo[t];
        for (int i = tid; i < H1 * 64; i += NTHREADS) {
            int n = i >> 6, p = i & 63;
            u32 o = (u32)(n * PITCH + 4 * p);
            *(u32*)(sm + OFF_BHI + o) = whi[i];
            *(u32*)(sm + OFF_BLO + o) = wlo[i];
        }
    }
    __syncthreads();   // s_atom visible

    // ---- gather features -> split bf16 A tiles (deep MLP: 8 LDG in flight) --
    {
        const int l = lane;
        #pragma unroll
        for (int r2 = 0; r2 < 4; r2++) {
            const int s = wid * 8 + r2 * 2;
            const float* rA = x + (size_t)s_atom[s] * XROW + 1;
            const float* rB = x + (size_t)s_atom[s + 1] * XROW + 1;
            const u32 oA = (u32)(s * PITCH);
            const u32 oB = (u32)((s + 1) * PITCH);
            if (l < 31) {
                float a0 = rA[4 * l], a1 = rA[4 * l + 1], a2 = rA[4 * l + 2], a3 = rA[4 * l + 3];
                float b0 = rB[4 * l], b1_ = rB[4 * l + 1], b2_ = rB[4 * l + 2], b3_ = rB[4 * l + 3];
                u32 ah0 = cvt2bf(a1, a0), ah1 = cvt2bf(a3, a2);
                u32 bh0 = cvt2bf(b1_, b0), bh1 = cvt2bf(b3_, b2_);
                float e;
                u32 al0, al1, bl0, bl1;
                e = __uint_as_float(ah0 << 16);
                float f = __uint_as_float(ah0 & 0xFFFF0000u);
                al0 = cvt2bf(a1 - f, a0 - e);
                e = __uint_as_float(ah1 << 16);
                f = __uint_as_float(ah1 & 0xFFFF0000u);
                al1 = cvt2bf(a3 - f, a2 - e);
                e = __uint_as_float(bh0 << 16);
                f = __uint_as_float(bh0 & 0xFFFF0000u);
                bl0 = cvt2bf(b1_ - f, b0 - e);
                e = __uint_as_float(bh1 << 16);
                f = __uint_as_float(bh1 & 0xFFFF0000u);
                bl1 = cvt2bf(b3_ - f, b2_ - e);
                *(u64*)(sm + OFF_AHI + oA + 8 * l) = pack64(ah0, ah1);
                *(u64*)(sm + OFF_ALO + oA + 8 * l) = pack64(al0, al1);
                *(u64*)(sm + OFF_AHI + oB + 8 * l) = pack64(bh0, bh1);
                *(u64*)(sm + OFF_ALO + oB + 8 * l) = pack64(bl0, bl1);
            } else {
                // lane 31: zero the k-pad (pairs 62,63 -> bytes 248..255)
                *(u64*)(sm + OFF_AHI + oA + 248) = 0ull;
                *(u64*)(sm + OFF_ALO + oA + 248) = 0ull;
                *(u64*)(sm + OFF_AHI + oB + 248) = 0ull;
                *(u64*)(sm + OFF_ALO + oB + 248) = 0ull;
            }
        }
    }
    __syncthreads();

    // ---- layer 1: warp tile 16 rows x 32 cols, split-bf16 mma.sync ----
    float acc[16];
    #pragma unroll
    for (int i = 0; i < 16; i++) acc[i] = 0.f;

    const int wg16   = (wid & 3) * 16;
    const int n_base = (wid >> 2) * 32;
    const u32 aoff = (u32)((wg16 + (lane & 15)) * PITCH + ((lane >> 4) * 16));
    const int b_n  = (lane & 7) + ((lane >> 4) << 3);
    const u32 boff = (u32)((n_base + b_n) * PITCH + (((lane >> 3) & 1) * 16));

    #pragma unroll
    for (int kc = 0; kc < 8; kc++) {
        const u32 kbyte = kc * 32;
        u32 aH[4], aL[4];
        ldmx4(aH, smb + OFF_AHI + aoff + kbyte);
        ldmx4(aL, smb + OFF_ALO + aoff + kbyte);
        #pragma unroll
        for (int q = 0; q < 2; q++) {           // q covers n-tiles 2q, 2q+1
            u32 bH[4], bL[4];
            const u32 bo = boff + (u32)(q * 16 * PITCH) + kbyte;
            ldmx4(bH, smb + OFF_BHI + bo);
            ldmx4(bL, smb + OFF_BLO + bo);
            float* d0 = acc + (2 * q) * 4;
            float* d1 = acc + (2 * q + 1) * 4;
            mma_bf16(d0, aH, bH[0], bH[1]);
            mma_bf16(d1, aH, bH[2], bH[3]);
            mma_bf16(d0, aH, bL[0], bL[1]);
            mma_bf16(d1, aH, bL[2], bL[3]);
            mma_bf16(d0, aL, bH[0], bH[1]);
            mma_bf16(d1, aL, bH[2], bH[3]);
        }
    }
    __syncthreads();   // all warps done reading A before h1 overwrites it

    // ---- bias + relu, write h1 rows (f32) into A_hi area ----
    {
        const int r0 = wg16 + (lane >> 2);
        const int c0 = (lane & 3) * 2;
        #pragma unroll
        for (int nt = 0; nt < 4; nt++) {
            const int col = n_base + nt * 8 + c0;
            const float bb0 = b1s[col], bb1 = b1s[col + 1];
            float2 v;
            v.x = fmaxf(acc[nt * 4 + 0] + bb0, 0.f);
            v.y = fmaxf(acc[nt * 4 + 1] + bb1, 0.f);
            *(float2*)(sm + OFF_AHI + r0 * PITCH + col * 4) = v;
            v.x = fmaxf(acc[nt * 4 + 2] + bb0, 0.f);
            v.y = fmaxf(acc[nt * 4 + 3] + bb1, 0.f);
            *(float2*)(sm + OFF_AHI + (r0 + 8) * PITCH + col * 4) = v;
        }
    }
    __syncthreads();

    // ---- layers 2+3 (8 warps x 8 atoms) ----
    {
        const int j = lane & 15;
        const float w3j = w3s[j];
        const float b2j = b2s[j];
        const float b3c = ((const float*)(sm + OFF_MISC))[0];
        const float cv  = ((const float*)(sm + OFF_MISC))[1];
        #pragma unroll
        for (int r = 0; r < 4; r++) {
            const int sloc = wid * 8 + 2 * r + (lane >> 4);
            const float* hr = (const float*)(sm + OFF_AHI + sloc * PITCH);
            const float* wr = &w2t[j * 68];
            float v = b2j;
            #pragma unroll
            for (int h4 = 0; h4 < H1 / 4; h4++) {
                float4 hv = *(const float4*)(hr + h4 * 4);
                float4 wv = *(const float4*)(wr + h4 * 4);
                v += hv.x * wv.x + hv.y * wv.y + hv.z * wv.z + hv.w * wv.w;
            }
            float partial = fmaxf(v, 0.f) * w3j;
            #pragma unroll
            for (int off = 8; off > 0; off >>= 1)
                partial += __shfl_xor_sync(0xffffffffu, partial, off);
            if (j == 0 && sloc < nvalid) {
                d_peratom[s_atom[sloc]] = (partial + b3c + cv) * s_mask[sloc];
            }
        }
    }
}

// ---------------- kernel 3: per-molecule reduction --------------------------
__global__ __launch_bounds__(256)
void reduce_kernel(float* __restrict__ out) {
    const int wid = threadIdx.x >> 5;
    const int lane = threadIdx.x & 31;
    const int mol = blockIdx.x * 8 + wid;
    if (mol >= BATCH) return;
    const float* p = d_peratom + (size_t)mol * ATOMS;
    float v = p[lane] + p[lane + 32];
    #pragma unroll
    for (int off = 16; off > 0; off >>= 1)
        v += __shfl_down_sync(0xffffffffu, v, off);
    if (lane == 0) out[mol] = v;
}

// ---------------- launch ----------------------------------------------------
extern "C" void kernel_launch(void* const* d_in, const int* in_sizes, int n_in,
                              void* d_out, int out_size) {
    const float* x    = (const float*)d_in[0];
    const float* mask = (const float*)d_in[1];
    const float* W1   = (const float*)d_in[2];
    const float* b1   = (const float*)d_in[3];
    const float* W2   = (const float*)d_in[4];
    const float* b2   = (const float*)d_in[5];
    const float* W3   = (const float*)d_in[6];
    const float* b3   = (const float*)d_in[7];
    float* out = (float*)d_out;

    prep_kernel<<<NTYPE, 256>>>(W1, b1, W2, b2, W3, b3);
    classify_kernel<<<NATOMS / CLS_ATOMS, 256>>>(x);

    static int smem_set = 0;
    if (!smem_set) {
        cudaFuncSetAttribute(mol_kernel, cudaFuncAttributeMaxDynamicSharedMemorySize,
                             SMEM_TOTAL);
        smem_set = 1;
    }
    dim3 grid(CHUNKS_PER_TYPE, NTYPE);
    mol_kernel<<<grid, NTHREADS, SMEM_TOTAL>>>(x, mask, W2, b1, b2, W3, b3);

    reduce_kernel<<<BATCH / 8, 256>>>(out);
}

// round 7
// speedup vs baseline: 3.1222x; 1.0490x over previous
#include <cuda_runtime.h>

typedef unsigned int       u32;
typedef unsigned long long u64;

#define BATCH    4096
#define ATOMS    64
#define NATOMS   (BATCH * ATOMS)
#define FDIM     124
#define XROW     125
#define NTYPE    8
#define H1       64
#define H2       16
#define NA       64                  // atoms per chunk
#define NTHREADS 256
#define LISTCAP  40960
#define NSLOT    37                  // 37*8 = 296 CTAs = 148 SMs x 2 CTAs

#define PITCHF   132                 // floats per row (bank-spread)

// ---------------- SMEM layout (float indices) --------------------------------
#define FA     0                      // A tile 64 x 132 f32 (feats, then h1)
#define FBH    (64 * PITCHF)          // B_hi 64(n) x 132(k) tf32 bits
#define FBL    (FBH + 64 * PITCHF)    // B_lo
#define FW2    (FBL + 64 * PITCHF)    // w2t [16][68]
#define FB1    (FW2 + 16 * 68)
#define FB2    (FB1 + 64)
#define FW3    (FB2 + 16)
#define FMASK  (FW3 + 16)
#define FATOM  (FMASK + 64)
#define FMISC  (FATOM + 64)
#define SMEM_FLOATS (FMISC + 4)
#define SMEM_TOTAL  (SMEM_FLOATS * 4)    // ~106.7 KB -> 2 CTAs/SM

// ---------------- device globals ---------------------------------------------
__device__ float d_corr[NTYPE];
__device__ int   d_cnt[NTYPE];
__device__ int   d_list[NTYPE][LISTCAP];
__device__ u32   d_w1hi[NTYPE][H1 * 128];   // [t][n][k] tf32 bits, k padded 128
__device__ u32   d_w1lo[NTYPE][H1 * 128];

// ---------------- helpers ----------------------------------------------------
__device__ __forceinline__ u32 rna_tf32(float v) {
    return (__float_as_uint(v) + 0x1000u) & 0xFFFFE000u;
}
__device__ __forceinline__ void mma_tf32(float* d, u32 a0, u32 a1, u32 a2, u32 a3,
                                         u32 b0, u32 b1) {
    asm volatile(
        "mma.sync.aligned.m16n8k8.row.col.f32.tf32.tf32.f32 "
        "{%0,%1,%2,%3}, {%4,%5,%6,%7}, {%8,%9}, {%0,%1,%2,%3};"
        : "+f"(d[0]), "+f"(d[1]), "+f"(d[2]), "+f"(d[3])
        : "r"(a0), "r"(a1), "r"(a2), "r"(a3), "r"(b0), "r"(b1));
}

// ---------------- kernel 0: prep (W1 hi/lo tf32 split, corr, counters) ------
__global__ __launch_bounds__(256)
void prep_kernel(const float* __restrict__ W1,
                 const float* __restrict__ b1,
                 const float* __restrict__ W2,
                 const float* __restrict__ b2,
                 const float* __restrict__ W3,
                 const float* __restrict__ b3) {
    const int t = blockIdx.x;
    for (int i = threadIdx.x; i < H1 * 128; i += 256) {
        int n = i >> 7, k = i & 127;
        u32 hb = 0, lb = 0;
        if (k < FDIM) {
            float v = W1[(size_t)t * FDIM * H1 + k * H1 + n];
            hb = rna_tf32(v);
            float lo = v - __uint_as_float(hb);
            lb = rna_tf32(lo);
        }
        d_w1hi[t][i] = hb;
        d_w1lo[t][i] = lb;
    }
    if (blockIdx.x == 0) {
        __shared__ float c[NTYPE];
        int u = threadIdx.x;
        if (u < NTYPE) {
            d_cnt[u] = 0;
            float h1v[H1];
            #pragma unroll
            for (int j = 0; j < H1; j++) h1v[j] = fmaxf(b1[u * H1 + j], 0.f);
            float o = b3[u];
            for (int g = 0; g < H2; g++) {
                float v = b2[u * H2 + g];
                #pragma unroll
                for (int h = 0; h < H1; h++) v += h1v[h] * W2[u * H1 * H2 + h * H2 + g];
                o += fmaxf(v, 0.f) * W3[u * H2 + g];
            }
            c[u] = o;
        }
        __syncthreads();
        if (u < NTYPE) {
            float tot = 0.f;
            #pragma unroll
            for (int v = 0; v < NTYPE; v++) tot += c[v];
            d_corr[u] = tot - c[u];
        }
    }
}

// ---------------- kernel 0b: zero the output ---------------------------------
__global__ void zero_kernel(float* __restrict__ out) {
    int i = blockIdx.x * 512 + threadIdx.x;
    if (i < BATCH) out[i] = 0.f;
}

// ---------------- kernel 1: classify (smem-aggregated atomics) ---------------
#define CLS_ATOMS 1024
__global__ __launch_bounds__(256)
void classify_kernel(const float* __restrict__ x) {
    __shared__ int s_cnt[NTYPE];
    __shared__ int s_base[NTYPE];
    const int tid = threadIdx.x;
    if (tid < NTYPE) s_cnt[tid] = 0;
    __syncthreads();
    const int a0 = blockIdx.x * CLS_ATOMS + tid * 4;
    int ty[4], rk[4];
    float tf0 = x[(size_t)(a0 + 0) * XROW];
    float tf1 = x[(size_t)(a0 + 1) * XROW];
    float tf2 = x[(size_t)(a0 + 2) * XROW];
    float tf3 = x[(size_t)(a0 + 3) * XROW];
    ty[0] = (int)tf0; ty[1] = (int)tf1; ty[2] = (int)tf2; ty[3] = (int)tf3;
    #pragma unroll
    for (int i = 0; i < 4; i++) rk[i] = atomicAdd(&s_cnt[ty[i]], 1);
    __syncthreads();
    if (tid < NTYPE) s_base[tid] = atomicAdd(&d_cnt[tid], s_cnt[tid]);
    __syncthreads();
    #pragma unroll
    for (int i = 0; i < 4; i++)
        d_list[ty[i]][s_base[ty[i]] + rk[i]] = a0 + i;
}

// ---------------- kernel 2: persistent per-type split-tf32 MMA MLP -----------
__global__ __launch_bounds__(NTHREADS, 2)
void mol_kernel(const float* __restrict__ x,
                const float* __restrict__ mask,
                const float* __restrict__ W2,
                const float* __restrict__ b1,
                const float* __restrict__ b2,
                const float* __restrict__ W3,
                const float* __restrict__ b3,
                float* __restrict__ out) {
    extern __shared__ float sm[];
    const int tid = threadIdx.x, wid = tid >> 5, lane = tid & 31;
    const int t = blockIdx.y;
    const int cnt = d_cnt[t];

    float* A    = sm + FA;
    u32*   BH   = (u32*)(sm + FBH);
    u32*   BL   = (u32*)(sm + FBL);
    float* w2t  = sm + FW2;
    float* b1s  = sm + FB1;
    float* b2s  = sm + FB2;
    float* w3s  = sm + FW3;
    float* s_mk = sm + FMASK;
    int*   s_at = (int*)(sm + FATOM);

    // ---- stage per-type constants ONCE per persistent CTA ----
    {
        const u32* whi = d_w1hi[t];
        const u32* wlo = d_w1lo[t];
        for (int i = tid; i < H1 * 128; i += NTHREADS) {
            int n = i >> 7, k = i & 127;
            BH[n * PITCHF + k] = whi[i];
            BL[n * PITCHF + k] = wlo[i];
        }
        for (int i = tid; i < H1 * H2; i += NTHREADS) {
            int h = i >> 4, j = i & 15;
            w2t[j * 68 + h] = W2[(size_t)t * H1 * H2 + i];
        }
        if (tid < H1) b1s[tid] = b1[t * H1 + tid];
        if (tid < H2) { b2s[tid] = b2[t * H2 + tid]; w3s[tid] = W3[t * H2 + tid]; }
        if (tid == 0) sm[FMISC] = d_corr[t];
        // zero A pad columns 124..131 (never overwritten afterwards)
        for (int i = tid; i < NA * 8; i += NTHREADS) {
            int r = i >> 3, c = 124 + (i & 7);
            A[r * PITCHF + c] = 0.f;
        }
    }
    const float b3c = b3[t];

    // ---- persistent chunk loop ----
    for (int base = blockIdx.x * NA; base < cnt; base += NSLOT * NA) {
        const int nvalid = min(NA, cnt - base);
        __syncthreads();   // previous epilogue done before overwriting s_at / A

        if (tid < NA) {
            int idx = min(base + tid, cnt - 1);
            int a = d_list[t][idx];
            s_at[tid] = a;
            s_mk[tid] = mask[a];
        }
        __syncthreads();   // s_at visible

        // ---- gather features: pure f32 copy, 8 LDG.128 in flight ----
        {
            #pragma unroll
            for (int rr = 0; rr < 8; rr += 2) {
                const int s0 = wid * 8 + rr;
                const float* r0 = x + (size_t)s_at[s0] * XROW + 1;
                const float* r1 = x + (size_t)s_at[s0 + 1] * XROW + 1;
                if (lane < 31) {
                    const int l4 = lane * 4;
                    float a0 = r0[l4], a1 = r0[l4 + 1], a2 = r0[l4 + 2], a3 = r0[l4 + 3];
                    float c0 = r1[l4], c1 = r1[l4 + 1], c2 = r1[l4 + 2], c3 = r1[l4 + 3];
                    *(float4*)(A + s0 * PITCHF + l4)       = make_float4(a0, a1, a2, a3);
                    *(float4*)(A + (s0 + 1) * PITCHF + l4) = make_float4(c0, c1, c2, c3);
                }
            }
        }
        __syncthreads();   // A tile complete

        // ---- layer 1: warps 0..3, 16 rows x 64 cols, 3-pass split-tf32 ----
        if (wid < 4) {
            float acc[32];
            #pragma unroll
            for (int i = 0; i < 32; i++) acc[i] = 0.f;

            const int r1a = wid * 16 + (lane >> 2);
            const int ka  = lane & 3;
            const int nb  = lane >> 2;

            #pragma unroll 2
            for (int ks = 0; ks < 16; ks++) {
                const int kc = ks * 8 + ka;
                // correct m16n8k8 A fragment: a0=(r,k) a1=(r+8,k) a2=(r,k+4) a3=(r+8,k+4)
                float v0 = A[r1a * PITCHF + kc];
                float v1 = A[(r1a + 8) * PITCHF + kc];
                float v2 = A[r1a * PITCHF + kc + 4];
                float v3 = A[(r1a + 8) * PITCHF + kc + 4];
                u32 h0 = rna_tf32(v0), h1_ = rna_tf32(v1);
                u32 h2_ = rna_tf32(v2), h3_ = rna_tf32(v3);
                u32 l0 = __float_as_uint(v0 - __uint_as_float(h0));
                u32 l1 = __float_as_uint(v1 - __uint_as_float(h1_));
                u32 l2 = __float_as_uint(v2 - __uint_as_float(h2_));
                u32 l3 = __float_as_uint(v3 - __uint_as_float(h3_));
                #pragma unroll
                for (int nt = 0; nt < 8; nt++) {
                    const int bi = (nt * 8 + nb) * PITCHF + kc;
                    u32 bh0 = BH[bi], bh1 = BH[bi + 4];
                    u32 bl0 = BL[bi], bl1 = BL[bi + 4];
                    float* d = acc + nt * 4;
                    mma_tf32(d, h0, h1_, h2_, h3_, bh0, bh1);
                    mma_tf32(d, h0, h1_, h2_, h3_, bl0, bl1);
                    mma_tf32(d, l0, l1, l2, l3, bh0, bh1);
                }
            }
            // bias + relu -> write h1 into OWN A rows (warp-local)
            const int cbase = (lane & 3) * 2;
            #pragma unroll
            for (int nt = 0; nt < 8; nt++) {
                const int c = nt * 8 + cbase;
                const float bb0 = b1s[c], bb1 = b1s[c + 1];
                float2 v;
                v.x = fmaxf(acc[nt * 4 + 0] + bb0, 0.f);
                v.y = fmaxf(acc[nt * 4 + 1] + bb1, 0.f);
                *(float2*)(A + r1a * PITCHF + c) = v;
                v.x = fmaxf(acc[nt * 4 + 2] + bb0, 0.f);
                v.y = fmaxf(acc[nt * 4 + 3] + bb1, 0.f);
                *(float2*)(A + (r1a + 8) * PITCHF + c) = v;
            }
        }
        __syncthreads();   // h1 visible to all

        // ---- layers 2+3: 8 warps x 8 atoms, atomicAdd into out ----
        {
            const int j = lane & 15;
            const float w3j = w3s[j];
            const float b2j = b2s[j];
            const float cv  = sm[FMISC];
            #pragma unroll
            for (int r = 0; r < 4; r++) {
                const int sloc = wid * 8 + 2 * r + (lane >> 4);
                const float* hr = A + sloc * PITCHF;
                const float* wr = w2t + j * 68;
                float v = b2j;
                #pragma unroll
                for (int h4 = 0; h4 < H1 / 4; h4++) {
                    float4 hv = *(const float4*)(hr + h4 * 4);
                    float4 wv = *(const float4*)(wr + h4 * 4);
                    v += hv.x * wv.x + hv.y * wv.y + hv.z * wv.z + hv.w * wv.w;
                }
                float partial = fmaxf(v, 0.f) * w3j;
                #pragma unroll
                for (int off = 8; off > 0; off >>= 1)
                    partial += __shfl_xor_sync(0xffffffffu, partial, off);
                if (j == 0 && sloc < nvalid) {
                    int atom = s_at[sloc];
                    float val = (partial + b3c + cv) * s_mk[sloc];
                    atomicAdd(&out[atom >> 6], val);
                }
            }
        }
    }
}

// ---------------- launch -----------------------------------------------------
extern "C" void kernel_launch(void* const* d_in, const int* in_sizes, int n_in,
                              void* d_out, int out_size) {
    const float* x    = (const float*)d_in[0];
    const float* mask = (const float*)d_in[1];
    const float* W1   = (const float*)d_in[2];
    const float* b1   = (const float*)d_in[3];
    const float* W2   = (const float*)d_in[4];
    const float* b2   = (const float*)d_in[5];
    const float* W3   = (const float*)d_in[6];
    const float* b3   = (const float*)d_in[7];
    float* out = (float*)d_out;

    prep_kernel<<<NTYPE, 256>>>(W1, b1, W2, b2, W3, b3);
    zero_kernel<<<(BATCH + 511) / 512, 512>>>(out);
    classify_kernel<<<NATOMS / CLS_ATOMS, 256>>>(x);

    static int smem_set = 0;
    if (!smem_set) {
        cudaFuncSetAttribute(mol_kernel, cudaFuncAttributeMaxDynamicSharedMemorySize,
                             SMEM_TOTAL);
        smem_set = 1;
    }
    dim3 grid(NSLOT, NTYPE);
    mol_kernel<<<grid, NTHREADS, SMEM_TOTAL>>>(x, mask, W2, b1, b2, W3, b3, out);
}

// round 8
// speedup vs baseline: 4.3887x; 1.4056x over previous
#include <cuda_runtime.h>
#include <cuda_bf16.h>

typedef unsigned int       u32;
typedef unsigned long long u64;

#define BATCH    4096
#define ATOMS    64
#define NATOMS   (BATCH * ATOMS)
#define FDIM     124
#define XROW     125
#define NTYPE    8
#define H1       64
#define H2       16
#define NA       64                  // atoms per chunk
#define NTHREADS 256
#define LISTCAP  40960
#define NSLOT    55                  // 55*8 = 440 CTAs ~= 148 SMs x 3

#define APITCH   132                 // f32 per A row
#define BPITCH   68                  // u32 per B row (64 kpairs + pad)
#define W2PITCH  36                  // u32 per W2 row (32 kpairs + pad)

// ---------------- SMEM layout (float/u32 indices into dynamic smem) ----------
#define FA     0                               // A: 64 x 132 f32
#define FBH    (64 * APITCH)                   // BH: 64 x 68 u32
#define FBL    (FBH + 64 * BPITCH)
#define FW2H   (FBL + 64 * BPITCH)             // W2H: 16 x 36 u32
#define FW2L   (FW2H + 16 * W2PITCH)
#define FB1    (FW2L + 16 * W2PITCH)           // 64
#define FB2    (FB1 + 64)                      // 16
#define FW3    (FB2 + 16)                      // 16
#define FMASK  (FW3 + 16)                      // 64
#define FATOM  (FMASK + 64)                    // 64 (int)
#define FPART  (FATOM + 64)                    // 128 (s_part[64][2])
#define FMISC  (FPART + 128)                   // 2
#define SMEM_WORDS (FMISC + 2)
#define SMEM_TOTAL (SMEM_WORDS * 4)            // ~74.7 KB -> 3 CTAs/SM

// ---------------- device globals ---------------------------------------------
__device__ float d_corr[NTYPE];
__device__ int   d_cnt[NTYPE];
__device__ int   d_list[NTYPE][LISTCAP];
__device__ u32   d_w1hi[NTYPE][H1 * 64];   // [t][n][kpair]; k padded to 128
__device__ u32   d_w1lo[NTYPE][H1 * 64];
__device__ u32   d_w2hi[NTYPE][H2 * 32];   // [t][j][hpair]
__device__ u32   d_w2lo[NTYPE][H2 * 32];

// ---------------- helpers ----------------------------------------------------
__device__ __forceinline__ u32 cvt2bf(float hi_elem, float lo_elem) {
    u32 r;
    asm("cvt.rn.bf16x2.f32 %0, %1, %2;" : "=r"(r) : "f"(hi_elem), "f"(lo_elem));
    return r;
}
__device__ __forceinline__ void split2(float fx, float fy, u32& hi, u32& lo) {
    hi = cvt2bf(fy, fx);
    float ha = __uint_as_float(hi << 16);
    float hb = __uint_as_float(hi & 0xFFFF0000u);
    lo = cvt2bf(fy - hb, fx - ha);
}
__device__ __forceinline__ void mma16(float* d, u32 a0, u32 a1, u32 a2, u32 a3,
                                      u32 b0, u32 b1) {
    asm volatile(
        "mma.sync.aligned.m16n8k16.row.col.f32.bf16.bf16.f32 "
        "{%0,%1,%2,%3}, {%4,%5,%6,%7}, {%8,%9}, {%0,%1,%2,%3};"
        : "+f"(d[0]), "+f"(d[1]), "+f"(d[2]), "+f"(d[3])
        : "r"(a0), "r"(a1), "r"(a2), "r"(a3), "r"(b0), "r"(b1));
}

// ---------------- kernel 0: prep (weight splits, corr, counters, zero out) ---
__global__ __launch_bounds__(256)
void prep_kernel(const float* __restrict__ W1,
                 const float* __restrict__ b1,
                 const float* __restrict__ W2,
                 const float* __restrict__ b2,
                 const float* __restrict__ W3,
                 const float* __restrict__ b3,
                 float* __restrict__ out) {
    const int t = blockIdx.x;
    // W1 -> [n][kpair] bf16 hi/lo
    for (int i = threadIdx.x; i < H1 * 64; i += 256) {
        int n = i >> 6, p = i & 63;
        u32 hb = 0, lb = 0;
        if (p < FDIM / 2) {
            float va = W1[(size_t)t * FDIM * H1 + (2 * p) * H1 + n];
            float vb = W1[(size_t)t * FDIM * H1 + (2 * p + 1) * H1 + n];
            split2(va, vb, hb, lb);
        }
        d_w1hi[t][i] = hb;
        d_w1lo[t][i] = lb;
    }
    // W2 -> [j][hpair] bf16 hi/lo
    for (int i = threadIdx.x; i < H2 * 32; i += 256) {
        int j = i >> 5, p = i & 31;
        float va = W2[(size_t)t * H1 * H2 + (2 * p) * H2 + j];
        float vb = W2[(size_t)t * H1 * H2 + (2 * p + 1) * H2 + j];
        u32 hb, lb;
        split2(va, vb, hb, lb);
        d_w2hi[t][i] = hb;
        d_w2lo[t][i] = lb;
    }
    // zero output slice
    for (int i = threadIdx.x; i < BATCH / NTYPE; i += 256)
        out[t * (BATCH / NTYPE) + i] = 0.f;
    // block 0: counters + corrections
    if (t == 0) {
        __shared__ float c[NTYPE];
        int u = threadIdx.x;
        if (u < NTYPE) {
            d_cnt[u] = 0;
            float h1v[H1];
            #pragma unroll
            for (int j = 0; j < H1; j++) h1v[j] = fmaxf(b1[u * H1 + j], 0.f);
            float o = b3[u];
            for (int g = 0; g < H2; g++) {
                float v = b2[u * H2 + g];
                #pragma unroll
                for (int h = 0; h < H1; h++) v += h1v[h] * W2[u * H1 * H2 + h * H2 + g];
                o += fmaxf(v, 0.f) * W3[u * H2 + g];
            }
            c[u] = o;
        }
        __syncthreads();
        if (u < NTYPE) {
            float tot = 0.f;
            #pragma unroll
            for (int v = 0; v < NTYPE; v++) tot += c[v];
            d_corr[u] = tot - c[u];
        }
    }
}

// ---------------- kernel 1: classify (smem-aggregated atomics) ---------------
#define CLS_ATOMS 1024
__global__ __launch_bounds__(256)
void classify_kernel(const float* __restrict__ x) {
    __shared__ int s_cnt[NTYPE];
    __shared__ int s_base[NTYPE];
    const int tid = threadIdx.x;
    if (tid < NTYPE) s_cnt[tid] = 0;
    __syncthreads();
    const int a0 = blockIdx.x * CLS_ATOMS + tid * 4;
    int ty[4], rk[4];
    float tf0 = x[(size_t)(a0 + 0) * XROW];
    float tf1 = x[(size_t)(a0 + 1) * XROW];
    float tf2 = x[(size_t)(a0 + 2) * XROW];
    float tf3 = x[(size_t)(a0 + 3) * XROW];
    ty[0] = (int)tf0; ty[1] = (int)tf1; ty[2] = (int)tf2; ty[3] = (int)tf3;
    #pragma unroll
    for (int i = 0; i < 4; i++) rk[i] = atomicAdd(&s_cnt[ty[i]], 1);
    __syncthreads();
    if (tid < NTYPE) s_base[tid] = atomicAdd(&d_cnt[tid], s_cnt[tid]);
    __syncthreads();
    #pragma unroll
    for (int i = 0; i < 4; i++)
        d_list[ty[i]][s_base[ty[i]] + rk[i]] = a0 + i;
}

// ---------------- kernel 2: persistent per-type split-bf16 MMA MLP -----------
__global__ __launch_bounds__(NTHREADS, 3)
void mol_kernel(const float* __restrict__ x,
                const float* __restrict__ mask,
                const float* __restrict__ b1,
                const float* __restrict__ b2,
                const float* __restrict__ W3,
                const float* __restrict__ b3,
                float* __restrict__ out) {
    extern __shared__ float sm[];
    const int tid = threadIdx.x, wid = tid >> 5, lane = tid & 31;
    const int t = blockIdx.y;
    const int cnt = d_cnt[t];

    float* A    = sm + FA;
    u32*   BH   = (u32*)(sm + FBH);
    u32*   BL   = (u32*)(sm + FBL);
    u32*   W2H  = (u32*)(sm + FW2H);
    u32*   W2L  = (u32*)(sm + FW2L);
    float* b1s  = sm + FB1;
    float* b2s  = sm + FB2;
    float* w3s  = sm + FW3;
    float* s_mk = sm + FMASK;
    int*   s_at = (int*)(sm + FATOM);
    float* s_pt = sm + FPART;

    // ---- stage per-type constants ONCE per persistent CTA ----
    {
        const u32* whi = d_w1hi[t];
        const u32* wlo = d_w1lo[t];
        for (int i = tid; i < H1 * 64; i += NTHREADS) {
            int n = i >> 6, p = i & 63;
            BH[n * BPITCH + p] = whi[i];
            BL[n * BPITCH + p] = wlo[i];
        }
        const u32* v2h = d_w2hi[t];
        const u32* v2l = d_w2lo[t];
        for (int i = tid; i < H2 * 32; i += NTHREADS) {
            int j = i >> 5, p = i & 31;
            W2H[j * W2PITCH + p] = v2h[i];
            W2L[j * W2PITCH + p] = v2l[i];
        }
        if (tid < H1) b1s[tid] = b1[t * H1 + tid];
        if (tid < H2) { b2s[tid] = b2[t * H2 + tid]; w3s[tid] = W3[t * H2 + tid]; }
        if (tid == 0) { sm[FMISC] = d_corr[t]; sm[FMISC + 1] = b3[t]; }
        // zero A pad cols 124..131 (never overwritten)
        for (int i = tid; i < NA * 8; i += NTHREADS) {
            int r = i >> 3, c = 124 + (i & 7);
            A[r * APITCH + c] = 0.f;
        }
    }

    const int wm  = wid & 3;          // layer-1 m-tile
    const int wh  = wid >> 2;         // layer-1 n-half
    const int wm2 = wid >> 1;         // layer-2 m-tile
    const int wnt = wid & 1;          // layer-2 n-tile
    const int rr4 = lane >> 2;        // fragment row within tile
    const int ka  = lane & 3;

    // ---- persistent chunk loop ----
    for (int base = blockIdx.x * NA; base < cnt; base += NSLOT * NA) {
        const int nvalid = min(NA, cnt - base);
        __syncthreads();   // prior chunk fully consumed

        if (tid < NA) {
            int idx = min(base + tid, cnt - 1);
            int a = d_list[t][idx];
            s_at[tid] = a;
            s_mk[tid] = mask[a];
        }
        __syncthreads();

        // ---- gather features (pure f32 copy; 8 LDG.128 in flight) ----
        {
            #pragma unroll
            for (int rr = 0; rr < 8; rr += 2) {
                const int s0 = wid * 8 + rr;
                const float* r0 = x + (size_t)s_at[s0] * XROW + 1;
                const float* r1 = x + (size_t)s_at[s0 + 1] * XROW + 1;
                if (lane < 31) {
                    const int l4 = lane * 4;
                    float a0 = r0[l4], a1 = r0[l4 + 1], a2 = r0[l4 + 2], a3 = r0[l4 + 3];
                    float c0 = r1[l4], c1 = r1[l4 + 1], c2 = r1[l4 + 2], c3 = r1[l4 + 3];
                    *(float4*)(A + s0 * APITCH + l4)       = make_float4(a0, a1, a2, a3);
                    *(float4*)(A + (s0 + 1) * APITCH + l4) = make_float4(c0, c1, c2, c3);
                }
            }
        }
        __syncthreads();

        // ---- layer 1: 8 warps, each 16 rows x 32 cols, 3-pass split-bf16 ----
        float acc[16];
        #pragma unroll
        for (int i = 0; i < 16; i++) acc[i] = 0.f;
        {
            const int r = wm * 16 + rr4;
            #pragma unroll
            for (int ks = 0; ks < 8; ks++) {
                const int kb = 16 * ks + 2 * ka;
                float2 f0 = *(const float2*)(A + r * APITCH + kb);
                float2 f1 = *(const float2*)(A + (r + 8) * APITCH + kb);
                float2 f2 = *(const float2*)(A + r * APITCH + kb + 8);
                float2 f3 = *(const float2*)(A + (r + 8) * APITCH + kb + 8);
                u32 ah0, al0, ah1, al1, ah2, al2, ah3, al3;
                split2(f0.x, f0.y, ah0, al0);
                split2(f1.x, f1.y, ah1, al1);
                split2(f2.x, f2.y, ah2, al2);
                split2(f3.x, f3.y, ah3, al3);
                const int pidx = ks * 8 + ka;
                #pragma unroll
                for (int nt = 0; nt < 4; nt++) {
                    const int nrow = wh * 32 + nt * 8 + rr4;
                    const int bi = nrow * BPITCH + pidx;
                    u32 bh0 = BH[bi], bh1 = BH[bi + 4];
                    u32 bl0 = BL[bi], bl1 = BL[bi + 4];
                    float* d = acc + nt * 4;
                    mma16(d, ah0, ah1, ah2, ah3, bh0, bh1);
                    mma16(d, ah0, ah1, ah2, ah3, bl0, bl1);
                    mma16(d, al0, al1, al2, al3, bh0, bh1);
                }
            }
        }
        __syncthreads();   // everyone done reading feature cols

        // ---- bias + relu, write h1 (f32) into A cols 0..63 ----
        {
            const int r = wm * 16 + rr4;
            #pragma unroll
            for (int nt = 0; nt < 4; nt++) {
                const int c = wh * 32 + nt * 8 + ka * 2;
                const float bb0 = b1s[c], bb1 = b1s[c + 1];
                float2 v;
                v.x = fmaxf(acc[nt * 4 + 0] + bb0, 0.f);
                v.y = fmaxf(acc[nt * 4 + 1] + bb1, 0.f);
                *(float2*)(A + r * APITCH + c) = v;
                v.x = fmaxf(acc[nt * 4 + 2] + bb0, 0.f);
                v.y = fmaxf(acc[nt * 4 + 3] + bb1, 0.f);
                *(float2*)(A + (r + 8) * APITCH + c) = v;
            }
        }
        __syncthreads();   // h1 visible

        // ---- layer 2 (MMA) + layer 3: 8 warps, each m16n8 tile -------------
        {
            float a2c[4] = {0.f, 0.f, 0.f, 0.f};
            const int r = wm2 * 16 + rr4;
            #pragma unroll
            for (int ks = 0; ks < 4; ks++) {
                const int kb = 16 * ks + 2 * ka;
                float2 f0 = *(const float2*)(A + r * APITCH + kb);
                float2 f1 = *(const float2*)(A + (r + 8) * APITCH + kb);
                float2 f2 = *(const float2*)(A + r * APITCH + kb + 8);
                float2 f3 = *(const float2*)(A + (r + 8) * APITCH + kb + 8);
                u32 ah0, al0, ah1, al1, ah2, al2, ah3, al3;
                split2(f0.x, f0.y, ah0, al0);
                split2(f1.x, f1.y, ah1, al1);
                split2(f2.x, f2.y, ah2, al2);
                split2(f3.x, f3.y, ah3, al3);
                const int pidx = ks * 8 + ka;
                const int nrow = wnt * 8 + rr4;
                const int bi = nrow * W2PITCH + pidx;
                u32 bh0 = W2H[bi], bh1 = W2H[bi + 4];
                u32 bl0 = W2L[bi], bl1 = W2L[bi + 4];
                mma16(a2c, ah0, ah1, ah2, ah3, bh0, bh1);
                mma16(a2c, ah0, ah1, ah2, ah3, bl0, bl1);
                mma16(a2c, al0, al1, al2, al3, bh0, bh1);
            }
            // layer 3 on D fragment
            const int j0 = wnt * 8 + ka * 2;
            const float w30 = w3s[j0], w31 = w3s[j0 + 1];
            const float bb0 = b2s[j0], bb1 = b2s[j0 + 1];
            float pr  = fmaxf(a2c[0] + bb0, 0.f) * w30 + fmaxf(a2c[1] + bb1, 0.f) * w31;
            float pr8 = fmaxf(a2c[2] + bb0, 0.f) * w30 + fmaxf(a2c[3] + bb1, 0.f) * w31;
            pr  += __shfl_xor_sync(0xffffffffu, pr, 1);
            pr  += __shfl_xor_sync(0xffffffffu, pr, 2);
            pr8 += __shfl_xor_sync(0xffffffffu, pr8, 1);
            pr8 += __shfl_xor_sync(0xffffffffu, pr8, 2);
            if (ka == 0) {
                s_pt[(r) * 2 + wnt]     = pr;
                s_pt[(r + 8) * 2 + wnt] = pr8;
            }
        }
        __syncthreads();

        // ---- combine + mask + atomic accumulate ----
        if (tid < NA && tid < nvalid) {
            float v = s_pt[tid * 2] + s_pt[tid * 2 + 1];
            float val = (v + sm[FMISC + 1] + sm[FMISC]) * s_mk[tid];
            atomicAdd(&out[s_at[tid] >> 6], val);
        }
    }
}

// ---------------- launch -----------------------------------------------------
extern "C" void kernel_launch(void* const* d_in, const int* in_sizes, int n_in,
                              void* d_out, int out_size) {
    const float* x    = (const float*)d_in[0];
    const float* mask = (const float*)d_in[1];
    const float* W1   = (const float*)d_in[2];
    const float* b1   = (const float*)d_in[3];
    const float* W2   = (const float*)d_in[4];
    const float* b2   = (const float*)d_in[5];
    const float* W3   = (const float*)d_in[6];
    const float* b3   = (const float*)d_in[7];
    float* out = (float*)d_out;

    prep_kernel<<<NTYPE, 256>>>(W1, b1, W2, b2, W3, b3, out);
    classify_kernel<<<NATOMS / CLS_ATOMS, 256>>>(x);

    static int smem_set = 0;
    if (!smem_set) {
        cudaFuncSetAttribute(mol_kernel, cudaFuncAttributeMaxDynamicSharedMemorySize,
                             SMEM_TOTAL);
        smem_set = 1;
    }
    dim3 grid(NSLOT, NTYPE);
    mol_kernel<<<grid, NTHREADS, SMEM_TOTAL>>>(x, mask, b1, b2, W3, b3, out);
}

// round 9
// speedup vs baseline: 5.0693x; 1.1551x over previous
#include <cuda_runtime.h>
#include <cuda_bf16.h>

typedef unsigned int       u32;
typedef unsigned long long u64;

#define BATCH    4096
#define ATOMS    64
#define NATOMS   (BATCH * ATOMS)
#define FDIM     124
#define XROW     125
#define NTYPE    8
#define H1       64
#define H2       16
#define NA       64                  // atoms per chunk
#define NTHREADS 256
#define LISTCAP  40960
#define NSLOT    55                  // 55*8 = 440 CTAs ~= 148 SMs x 3

#define APITCH   132                 // f32 per A row
#define BPITCH   68                  // u64 per B row (64 kpairs + pad)
#define W2PITCH  36                  // u64 per W2 row (32 hpairs + pad)

// ---------------- SMEM layout (byte offsets) ---------------------------------
#define OFF_BP    0                          // Bp  u64[64][68]  = 34816
#define OFF_W2P   34816                      // W2p u64[16][36]  = 4608
#define OFF_A     39424                      // A   f32[64][132] = 33792
#define OFF_B1    73216                      // 256
#define OFF_B2    73472                      // 64
#define OFF_W3    73536                      // 64
#define OFF_MASK  73600                      // 256
#define OFF_ATOM  73856                      // 256
#define OFF_PART  74112                      // 512
#define OFF_MISC  74624                      // 16
#define SMEM_TOTAL 74640                     // -> 3 CTAs/SM

// ---------------- device globals ---------------------------------------------
__device__ float d_c[NTYPE];               // c_t = MLP_t(0)
__device__ int   d_cnt[NTYPE];
__device__ int   d_list[NTYPE][LISTCAP];
__device__ u64   d_w1p[NTYPE][H1 * 64];    // [t][n][kpair] (lo<<32)|hi
__device__ u64   d_w2p[NTYPE][H2 * 32];    // [t][j][hpair]

// ---------------- helpers ----------------------------------------------------
__device__ __forceinline__ u32 cvt2bf(float hi_elem, float lo_elem) {
    u32 r;
    asm("cvt.rn.bf16x2.f32 %0, %1, %2;" : "=r"(r) : "f"(hi_elem), "f"(lo_elem));
    return r;
}
__device__ __forceinline__ void split2(float fx, float fy, u32& hi, u32& lo) {
    hi = cvt2bf(fy, fx);
    float ha = __uint_as_float(hi << 16);
    float hb = __uint_as_float(hi & 0xFFFF0000u);
    lo = cvt2bf(fy - hb, fx - ha);
}
__device__ __forceinline__ void mma16(float* d, u32 a0, u32 a1, u32 a2, u32 a3,
                                      u32 b0, u32 b1) {
    asm volatile(
        "mma.sync.aligned.m16n8k16.row.col.f32.bf16.bf16.f32 "
        "{%0,%1,%2,%3}, {%4,%5,%6,%7}, {%8,%9}, {%0,%1,%2,%3};"
        : "+f"(d[0]), "+f"(d[1]), "+f"(d[2]), "+f"(d[3])
        : "r"(a0), "r"(a1), "r"(a2), "r"(a3), "r"(b0), "r"(b1));
}
__device__ __forceinline__ u32 lo32(u64 v) { return (u32)v; }
__device__ __forceinline__ u32 hi32(u64 v) { return (u32)(v >> 32); }

// ---------------- kernel 0: fused setup (classify + weight prep) -------------
#define CLS_ATOMS 1024
#define CLS_BLOCKS (NATOMS / CLS_ATOMS)     // 256
__global__ __launch_bounds__(256)
void setup_kernel(const float* __restrict__ x,
                  const float* __restrict__ W1,
                  const float* __restrict__ b1,
                  const float* __restrict__ W2,
                  const float* __restrict__ b2,
                  const float* __restrict__ W3,
                  const float* __restrict__ b3,
                  float* __restrict__ out) {
    const int tid = threadIdx.x;
    if (blockIdx.x < CLS_BLOCKS) {
        // -------- classify 1024 atoms --------
        __shared__ int s_cnt[NTYPE];
        __shared__ int s_base[NTYPE];
        if (tid < NTYPE) s_cnt[tid] = 0;
        __syncthreads();
        const int a0 = blockIdx.x * CLS_ATOMS + tid * 4;
        int ty[4], rk[4];
        float tf0 = x[(size_t)(a0 + 0) * XROW];
        float tf1 = x[(size_t)(a0 + 1) * XROW];
        float tf2 = x[(size_t)(a0 + 2) * XROW];
        float tf3 = x[(size_t)(a0 + 3) * XROW];
        ty[0] = (int)tf0; ty[1] = (int)tf1; ty[2] = (int)tf2; ty[3] = (int)tf3;
        #pragma unroll
        for (int i = 0; i < 4; i++) rk[i] = atomicAdd(&s_cnt[ty[i]], 1);
        __syncthreads();
        if (tid < NTYPE) s_base[tid] = atomicAdd(&d_cnt[tid], s_cnt[tid]);
        __syncthreads();
        #pragma unroll
        for (int i = 0; i < 4; i++)
            d_list[ty[i]][s_base[ty[i]] + rk[i]] = a0 + i;
    } else {
        // -------- per-type weight prep (one block per type) --------
        const int t = blockIdx.x - CLS_BLOCKS;
        // W1 -> packed split bf16 [n][kpair]
        for (int i = tid; i < H1 * 64; i += 256) {
            int n = i >> 6, p = i & 63;
            u64 w = 0;
            if (p < FDIM / 2) {
                float va = W1[(size_t)t * FDIM * H1 + (2 * p) * H1 + n];
                float vb = W1[(size_t)t * FDIM * H1 + (2 * p + 1) * H1 + n];
                u32 hb, lb;
                split2(va, vb, hb, lb);
                w = ((u64)lb << 32) | hb;
            }
            d_w1p[t][i] = w;
        }
        // W2 -> packed split bf16 [j][hpair]
        for (int i = tid; i < H2 * 32; i += 256) {
            int j = i >> 5, p = i & 31;
            float va = W2[(size_t)t * H1 * H2 + (2 * p) * H2 + j];
            float vb = W2[(size_t)t * H1 * H2 + (2 * p + 1) * H2 + j];
            u32 hb, lb;
            split2(va, vb, hb, lb);
            d_w2p[t][i] = ((u64)lb << 32) | hb;
        }
        // zero output slice
        for (int i = tid; i < BATCH / NTYPE; i += 256)
            out[t * (BATCH / NTYPE) + i] = 0.f;
        // c_t = MLP_t(0): lanes 0..15 of warp 0, one H2 column each
        if (tid < 16) {
            const int g = tid;
            float v = b2[t * H2 + g];
            for (int h = 0; h < H1; h++)
                v += fmaxf(b1[t * H1 + h], 0.f) * W2[t * H1 * H2 + h * H2 + g];
            float o = fmaxf(v, 0.f) * W3[t * H2 + g];
            #pragma unroll
            for (int off = 8; off > 0; off >>= 1)
                o += __shfl_xor_sync(0xffffu, o, off);
            if (g == 0) d_c[t] = o + b3[t];
        }
    }
}

// ---------------- kernel 1: persistent per-type split-bf16 MMA MLP -----------
__global__ __launch_bounds__(NTHREADS, 3)
void mol_kernel(const float* __restrict__ x,
                const float* __restrict__ mask,
                const float* __restrict__ b1,
                const float* __restrict__ b2,
                const float* __restrict__ W3,
                const float* __restrict__ b3,
                float* __restrict__ out) {
    extern __shared__ char smraw[];
    const int tid = threadIdx.x, wid = tid >> 5, lane = tid & 31;
    const int t = blockIdx.y;
    const int cnt = d_cnt[t];

    u64*   Bp   = (u64*)(smraw + OFF_BP);
    u64*   W2p  = (u64*)(smraw + OFF_W2P);
    float* A    = (float*)(smraw + OFF_A);
    float* b1s  = (float*)(smraw + OFF_B1);
    float* b2s  = (float*)(smraw + OFF_B2);
    float* w3s  = (float*)(smraw + OFF_W3);
    float* s_mk = (float*)(smraw + OFF_MASK);
    int*   s_at = (int*)(smraw + OFF_ATOM);
    float* s_pt = (float*)(smraw + OFF_PART);
    float* s_ms = (float*)(smraw + OFF_MISC);

    // ---- stage per-type constants ONCE ----
    {
        const u64* w1 = d_w1p[t];
        for (int i = tid; i < H1 * 64; i += NTHREADS) {
            int n = i >> 6, p = i & 63;
            Bp[n * BPITCH + p] = w1[i];
        }
        const u64* w2 = d_w2p[t];
        for (int i = tid; i < H2 * 32; i += NTHREADS) {
            int j = i >> 5, p = i & 31;
            W2p[j * W2PITCH + p] = w2[i];
        }
        if (tid < H1) b1s[tid] = b1[t * H1 + tid];
        if (tid < H2) { b2s[tid] = b2[t * H2 + tid]; w3s[tid] = W3[t * H2 + tid]; }
        if (tid == 0) {
            float tot = 0.f;
            #pragma unroll
            for (int u = 0; u < NTYPE; u++) tot += d_c[u];
            // combined additive constant: b3 + corr, where corr = tot - c_t
            s_ms[0] = b3[t] + (tot - d_c[t]);
        }
        // zero A pad cols 124..131
        for (int i = tid; i < NA * 8; i += NTHREADS) {
            int r = i >> 3, c = 124 + (i & 7);
            A[r * APITCH + c] = 0.f;
        }
    }

    const int wm  = wid & 3;          // layer-1 m-tile
    const int wh  = wid >> 2;         // layer-1 n-half
    const int wm2 = wid >> 1;         // layer-2 m-tile
    const int wnt = wid & 1;          // layer-2 n-tile
    const int rr4 = lane >> 2;
    const int ka  = lane & 3;

    // ---- persistent chunk loop ----
    for (int base = blockIdx.x * NA; base < cnt; base += NSLOT * NA) {
        const int nvalid = min(NA, cnt - base);
        __syncthreads();   // prior chunk fully consumed

        if (tid < NA) {
            int idx = min(base + tid, cnt - 1);
            int a = d_list[t][idx];
            s_at[tid] = a;
            s_mk[tid] = mask[a];
        }
        __syncthreads();

        // ---- gather features (pure f32 copy; 8 LDG.128 in flight) ----
        {
            #pragma unroll
            for (int rr = 0; rr < 8; rr += 2) {
                const int s0 = wid * 8 + rr;
                const float* r0 = x + (size_t)s_at[s0] * XROW + 1;
                const float* r1 = x + (size_t)s_at[s0 + 1] * XROW + 1;
                if (lane < 31) {
                    const int l4 = lane * 4;
                    float a0 = r0[l4], a1 = r0[l4 + 1], a2 = r0[l4 + 2], a3 = r0[l4 + 3];
                    float c0 = r1[l4], c1 = r1[l4 + 1], c2 = r1[l4 + 2], c3 = r1[l4 + 3];
                    *(float4*)(A + s0 * APITCH + l4)       = make_float4(a0, a1, a2, a3);
                    *(float4*)(A + (s0 + 1) * APITCH + l4) = make_float4(c0, c1, c2, c3);
                }
            }
        }
        __syncthreads();

        // ---- layer 1: 8 warps, 16 rows x 32 cols each, 3-pass split-bf16 ----
        float acc[16];
        #pragma unroll
        for (int i = 0; i < 16; i++) acc[i] = 0.f;
        {
            const int r = wm * 16 + rr4;
            #pragma unroll
            for (int ks = 0; ks < 8; ks++) {
                const int kb = 16 * ks + 2 * ka;
                float2 f0 = *(const float2*)(A + r * APITCH + kb);
                float2 f1 = *(const float2*)(A + (r + 8) * APITCH + kb);
                float2 f2 = *(const float2*)(A + r * APITCH + kb + 8);
                float2 f3 = *(const float2*)(A + (r + 8) * APITCH + kb + 8);
                u32 ah0, al0, ah1, al1, ah2, al2, ah3, al3;
                split2(f0.x, f0.y, ah0, al0);
                split2(f1.x, f1.y, ah1, al1);
                split2(f2.x, f2.y, ah2, al2);
                split2(f3.x, f3.y, ah3, al3);
                const int pidx = ks * 8 + ka;
                #pragma unroll
                for (int nt = 0; nt < 4; nt++) {
                    const int nrow = wh * 32 + nt * 8 + rr4;
                    const int bi = nrow * BPITCH + pidx;
                    u64 bp0 = Bp[bi], bp1 = Bp[bi + 4];
                    float* d = acc + nt * 4;
                    mma16(d, ah0, ah1, ah2, ah3, lo32(bp0), lo32(bp1));
                    mma16(d, ah0, ah1, ah2, ah3, hi32(bp0), hi32(bp1));
                    mma16(d, al0, al1, al2, al3, lo32(bp0), lo32(bp1));
                }
            }
        }
        __syncthreads();   // all feature reads done

        // ---- bias + relu -> h1 into A cols 0..63 ----
        {
            const int r = wm * 16 + rr4;
            #pragma unroll
            for (int nt = 0; nt < 4; nt++) {
                const int c = wh * 32 + nt * 8 + ka * 2;
                const float bb0 = b1s[c], bb1 = b1s[c + 1];
                float2 v;
                v.x = fmaxf(acc[nt * 4 + 0] + bb0, 0.f);
                v.y = fmaxf(acc[nt * 4 + 1] + bb1, 0.f);
                *(float2*)(A + r * APITCH + c) = v;
                v.x = fmaxf(acc[nt * 4 + 2] + bb0, 0.f);
                v.y = fmaxf(acc[nt * 4 + 3] + bb1, 0.f);
                *(float2*)(A + (r + 8) * APITCH + c) = v;
            }
        }
        __syncthreads();   // h1 visible

        // ---- layer 2 (MMA) + layer 3 ----
        {
            float a2c[4] = {0.f, 0.f, 0.f, 0.f};
            const int r = wm2 * 16 + rr4;
            #pragma unroll
            for (int ks = 0; ks < 4; ks++) {
                const int kb = 16 * ks + 2 * ka;
                float2 f0 = *(const float2*)(A + r * APITCH + kb);
                float2 f1 = *(const float2*)(A + (r + 8) * APITCH + kb);
                float2 f2 = *(const float2*)(A + r * APITCH + kb + 8);
                float2 f3 = *(const float2*)(A + (r + 8) * APITCH + kb + 8);
                u32 ah0, al0, ah1, al1, ah2, al2, ah3, al3;
                split2(f0.x, f0.y, ah0, al0);
                split2(f1.x, f1.y, ah1, al1);
                split2(f2.x, f2.y, ah2, al2);
                split2(f3.x, f3.y, ah3, al3);
                const int pidx = ks * 8 + ka;
                const int nrow = wnt * 8 + rr4;
                const int bi = nrow * W2PITCH + pidx;
                u64 bp0 = W2p[bi], bp1 = W2p[bi + 4];
                mma16(a2c, ah0, ah1, ah2, ah3, lo32(bp0), lo32(bp1));
                mma16(a2c, ah0, ah1, ah2, ah3, hi32(bp0), hi32(bp1));
                mma16(a2c, al0, al1, al2, al3, lo32(bp0), lo32(bp1));
            }
            const int j0 = wnt * 8 + ka * 2;
            const float w30 = w3s[j0], w31 = w3s[j0 + 1];
            const float bb0 = b2s[j0], bb1 = b2s[j0 + 1];
            float pr  = fmaxf(a2c[0] + bb0, 0.f) * w30 + fmaxf(a2c[1] + bb1, 0.f) * w31;
            float pr8 = fmaxf(a2c[2] + bb0, 0.f) * w30 + fmaxf(a2c[3] + bb1, 0.f) * w31;
            pr  += __shfl_xor_sync(0xffffffffu, pr, 1);
            pr  += __shfl_xor_sync(0xffffffffu, pr, 2);
            pr8 += __shfl_xor_sync(0xffffffffu, pr8, 1);
            pr8 += __shfl_xor_sync(0xffffffffu, pr8, 2);
            if (ka == 0) {
                s_pt[r * 2 + wnt]       = pr;
                s_pt[(r + 8) * 2 + wnt] = pr8;
            }
        }
        __syncthreads();

        // ---- combine + mask + atomic accumulate ----
        if (tid < NA && tid < nvalid) {
            float v = s_pt[tid * 2] + s_pt[tid * 2 + 1];
            float val = (v + s_ms[0]) * s_mk[tid];
            atomicAdd(&out[s_at[tid] >> 6], val);
        }
    }
}

// ---------------- launch -----------------------------------------------------
extern "C" void kernel_launch(void* const* d_in, const int* in_sizes, int n_in,
                              void* d_out, int out_size) {
    const float* x    = (const float*)d_in[0];
    const float* mask = (const float*)d_in[1];
    const float* W1   = (const float*)d_in[2];
    const float* b1   = (const float*)d_in[3];
    const float* W2   = (const float*)d_in[4];
    const float* b2   = (const float*)d_in[5];
    const float* W3   = (const float*)d_in[6];
    const float* b3   = (const float*)d_in[7];
    float* out = (float*)d_out;

    static void* cnt_addr = nullptr;
    static int   init_done = 0;
    if (!init_done) {
        cudaGetSymbolAddress(&cnt_addr, d_cnt);
        cudaFuncSetAttribute(mol_kernel, cudaFuncAttributeMaxDynamicSharedMemorySize,
                             SMEM_TOTAL);
        init_done = 1;
    }

    cudaMemsetAsync(cnt_addr, 0, NTYPE * sizeof(int));
    setup_kernel<<<CLS_BLOCKS + NTYPE, 256>>>(x, W1, b1, W2, b2, W3, b3, out);

    dim3 grid(NSLOT, NTYPE);
    mol_kernel<<<grid, NTHREADS, SMEM_TOTAL>>>(x, mask, b1, b2, W3, b3, out);
}

// round 10
// speedup vs baseline: 5.4819x; 1.0814x over previous
#include <cuda_runtime.h>
#include <cuda_bf16.h>

typedef unsigned int       u32;
typedef unsigned long long u64;

#define BATCH    4096
#define ATOMS    64
#define NATOMS   (BATCH * ATOMS)
#define FDIM     124
#define XROW     125
#define NTYPE    8
#define H1       64
#define H2       16
#define NA       64                  // atoms per chunk
#define NTHREADS 256
#define LISTCAP  40960
#define NSLOT    55                  // 55*8 = 440 CTAs ~= 148 SMs x 3

#define AP       68                  // u64 per A row  (136 floats == 8 mod 32)
#define BPITCH   68                  // u64 per B row  (conflict-free, proven)
#define W2PITCH  36                  // u64 per W2 row

// ---------------- SMEM layout (byte offsets) ---------------------------------
#define OFF_BP    0                          // Bp  u64[64][68]  = 34816
#define OFF_W2P   34816                      // W2p u64[16][36]  = 4608
#define OFF_A     39424                      // A   u64[64][68]  = 34816 (split feats, then split h1)
#define OFF_B1    74240                      // 256
#define OFF_B2    74496                      // 64
#define OFF_W3    74560                      // 64
#define OFF_MASK  74624                      // 256
#define OFF_ATOM  74880                      // 256
#define OFF_PART  75136                      // 512
#define OFF_MISC  75648                      // 16
#define SMEM_TOTAL 75664                     // -> 3 CTAs/SM

// ---------------- device globals ---------------------------------------------
__device__ float d_c[NTYPE];               // c_t = MLP_t(0)
__device__ int   d_cnt[NTYPE];
__device__ int   d_list[NTYPE][LISTCAP];
__device__ u64   d_w1p[NTYPE][H1 * 64];    // [t][n][kpair] (lo<<32)|hi
__device__ u64   d_w2p[NTYPE][H2 * 32];    // [t][j][hpair]

// ---------------- helpers ----------------------------------------------------
__device__ __forceinline__ u32 cvt2bf(float hi_elem, float lo_elem) {
    u32 r;
    asm("cvt.rn.bf16x2.f32 %0, %1, %2;" : "=r"(r) : "f"(hi_elem), "f"(lo_elem));
    return r;
}
__device__ __forceinline__ u64 split_pack(float fx, float fy) {
    u32 hi = cvt2bf(fy, fx);
    float ha = __uint_as_float(hi << 16);
    float hb = __uint_as_float(hi & 0xFFFF0000u);
    u32 lo = cvt2bf(fy - hb, fx - ha);
    return ((u64)lo << 32) | hi;
}
__device__ __forceinline__ void mma16(float* d, u32 a0, u32 a1, u32 a2, u32 a3,
                                      u32 b0, u32 b1) {
    asm volatile(
        "mma.sync.aligned.m16n8k16.row.col.f32.bf16.bf16.f32 "
        "{%0,%1,%2,%3}, {%4,%5,%6,%7}, {%8,%9}, {%0,%1,%2,%3};"
        : "+f"(d[0]), "+f"(d[1]), "+f"(d[2]), "+f"(d[3])
        : "r"(a0), "r"(a1), "r"(a2), "r"(a3), "r"(b0), "r"(b1));
}
__device__ __forceinline__ u32 lo32(u64 v) { return (u32)v; }
__device__ __forceinline__ u32 hi32(u64 v) { return (u32)(v >> 32); }

// ---------------- kernel 0: fused setup (classify + weight prep) -------------
#define CLS_ATOMS 1024
#define CLS_BLOCKS (NATOMS / CLS_ATOMS)     // 256
__global__ __launch_bounds__(256)
void setup_kernel(const float* __restrict__ x,
                  const float* __restrict__ W1,
                  const float* __restrict__ b1,
                  const float* __restrict__ W2,
                  const float* __restrict__ b2,
                  const float* __restrict__ W3,
                  const float* __restrict__ b3,
                  float* __restrict__ out) {
    const int tid = threadIdx.x;
    if (blockIdx.x < CLS_BLOCKS) {
        __shared__ int s_cnt[NTYPE];
        __shared__ int s_base[NTYPE];
        if (tid < NTYPE) s_cnt[tid] = 0;
        __syncthreads();
        const int a0 = blockIdx.x * CLS_ATOMS + tid * 4;
        int ty[4], rk[4];
        float tf0 = x[(size_t)(a0 + 0) * XROW];
        float tf1 = x[(size_t)(a0 + 1) * XROW];
        float tf2 = x[(size_t)(a0 + 2) * XROW];
        float tf3 = x[(size_t)(a0 + 3) * XROW];
        ty[0] = (int)tf0; ty[1] = (int)tf1; ty[2] = (int)tf2; ty[3] = (int)tf3;
        #pragma unroll
        for (int i = 0; i < 4; i++) rk[i] = atomicAdd(&s_cnt[ty[i]], 1);
        __syncthreads();
        if (tid < NTYPE) s_base[tid] = atomicAdd(&d_cnt[tid], s_cnt[tid]);
        __syncthreads();
        #pragma unroll
        for (int i = 0; i < 4; i++)
            d_list[ty[i]][s_base[ty[i]] + rk[i]] = a0 + i;
    } else {
        const int t = blockIdx.x - CLS_BLOCKS;
        for (int i = tid; i < H1 * 64; i += 256) {
            int n = i >> 6, p = i & 63;
            u64 w = 0;
            if (p < FDIM / 2) {
                float va = W1[(size_t)t * FDIM * H1 + (2 * p) * H1 + n];
                float vb = W1[(size_t)t * FDIM * H1 + (2 * p + 1) * H1 + n];
                w = split_pack(va, vb);
            }
            d_w1p[t][i] = w;
        }
        for (int i = tid; i < H2 * 32; i += 256) {
            int j = i >> 5, p = i & 31;
            float va = W2[(size_t)t * H1 * H2 + (2 * p) * H2 + j];
            float vb = W2[(size_t)t * H1 * H2 + (2 * p + 1) * H2 + j];
            d_w2p[t][i] = split_pack(va, vb);
        }
        for (int i = tid; i < BATCH / NTYPE; i += 256)
            out[t * (BATCH / NTYPE) + i] = 0.f;
        if (tid < 16) {
            const int g = tid;
            float v = b2[t * H2 + g];
            for (int h = 0; h < H1; h++)
                v += fmaxf(b1[t * H1 + h], 0.f) * W2[t * H1 * H2 + h * H2 + g];
            float o = fmaxf(v, 0.f) * W3[t * H2 + g];
            #pragma unroll
            for (int off = 8; off > 0; off >>= 1)
                o += __shfl_xor_sync(0xffffu, o, off);
            if (g == 0) d_c[t] = o + b3[t];
        }
    }
}

// ---------------- kernel 1: persistent per-type split-bf16 MMA MLP -----------
__global__ __launch_bounds__(NTHREADS, 3)
void mol_kernel(const float* __restrict__ x,
                const float* __restrict__ mask,
                const float* __restrict__ b1,
                const float* __restrict__ b2,
                const float* __restrict__ W3,
                const float* __restrict__ b3,
                float* __restrict__ out) {
    extern __shared__ char smraw[];
    const int tid = threadIdx.x, wid = tid >> 5, lane = tid & 31;
    const int t = blockIdx.y;
    const int cnt = d_cnt[t];

    u64*   Bp   = (u64*)(smraw + OFF_BP);
    u64*   W2p  = (u64*)(smraw + OFF_W2P);
    u64*   Ap   = (u64*)(smraw + OFF_A);
    float* b1s  = (float*)(smraw + OFF_B1);
    float* b2s  = (float*)(smraw + OFF_B2);
    float* w3s  = (float*)(smraw + OFF_W3);
    float* s_mk = (float*)(smraw + OFF_MASK);
    int*   s_at = (int*)(smraw + OFF_ATOM);
    float* s_pt = (float*)(smraw + OFF_PART);
    float* s_ms = (float*)(smraw + OFF_MISC);

    // ---- stage per-type constants ONCE ----
    {
        const u64* w1 = d_w1p[t];
        for (int i = tid; i < H1 * 64; i += NTHREADS) {
            int n = i >> 6, p = i & 63;
            Bp[n * BPITCH + p] = w1[i];
        }
        const u64* w2 = d_w2p[t];
        for (int i = tid; i < H2 * 32; i += NTHREADS) {
            int j = i >> 5, p = i & 31;
            W2p[j * W2PITCH + p] = w2[i];
        }
        if (tid < H1) b1s[tid] = b1[t * H1 + tid];
        if (tid < H2) { b2s[tid] = b2[t * H2 + tid]; w3s[tid] = W3[t * H2 + tid]; }
        if (tid == 0) {
            float tot = 0.f;
            #pragma unroll
            for (int u = 0; u < NTYPE; u++) tot += d_c[u];
            s_ms[0] = b3[t] + (tot - d_c[t]);   // b3 + correction
        }
    }

    const int wm  = wid & 3;          // layer-1 m-tile
    const int wh  = wid >> 2;         // layer-1 n-half
    const int wm2 = wid >> 1;         // layer-2 m-tile
    const int wnt = wid & 1;          // layer-2 n-tile
    const int rr4 = lane >> 2;
    const int ka  = lane & 3;

    // ---- persistent chunk loop ----
    for (int base = blockIdx.x * NA; base < cnt; base += NSLOT * NA) {
        const int nvalid = min(NA, cnt - base);
        __syncthreads();   // prior chunk fully consumed

        if (tid < NA) {
            int idx = min(base + tid, cnt - 1);
            int a = d_list[t][idx];
            s_at[tid] = a;
            s_mk[tid] = mask[a];
        }
        __syncthreads();

        // ---- gather + split: features -> packed u64 (hi|lo) A tile ----
        {
            #pragma unroll
            for (int rr = 0; rr < 8; rr += 2) {
                const int s0 = wid * 8 + rr;
                const float* r0 = x + (size_t)s_at[s0] * XROW + 1;
                const float* r1 = x + (size_t)s_at[s0 + 1] * XROW + 1;
                if (lane < 31) {
                    const int l4 = lane * 4;
                    float a0 = r0[l4], a1 = r0[l4 + 1], a2 = r0[l4 + 2], a3 = r0[l4 + 3];
                    float c0 = r1[l4], c1 = r1[l4 + 1], c2 = r1[l4 + 2], c3 = r1[l4 + 3];
                    ulonglong2 wa, wc;
                    wa.x = split_pack(a0, a1); wa.y = split_pack(a2, a3);
                    wc.x = split_pack(c0, c1); wc.y = split_pack(c2, c3);
                    *(ulonglong2*)(Ap + s0 * AP + 2 * lane)       = wa;
                    *(ulonglong2*)(Ap + (s0 + 1) * AP + 2 * lane) = wc;
                } else {
                    // k-pad kpairs 62,63 -> zero
                    ulonglong2 z; z.x = 0ull; z.y = 0ull;
                    *(ulonglong2*)(Ap + s0 * AP + 62)       = z;
                    *(ulonglong2*)(Ap + (s0 + 1) * AP + 62) = z;
                }
            }
        }
        __syncthreads();

        // ---- layer 1: 8 warps, 16 rows x 32 cols each, 3-pass split-bf16 ----
        float acc[16];
        #pragma unroll
        for (int i = 0; i < 16; i++) acc[i] = 0.f;
        {
            const int r = wm * 16 + rr4;
            const u64* Ar0 = Ap + r * AP;
            const u64* Ar1 = Ap + (r + 8) * AP;
            #pragma unroll
            for (int ks = 0; ks < 8; ks++) {
                const int q = ks * 8 + ka;
                u64 w00 = Ar0[q], w01 = Ar0[q + 4];
                u64 w10 = Ar1[q], w11 = Ar1[q + 4];
                u32 ah0 = lo32(w00), ah1 = lo32(w10), ah2 = lo32(w01), ah3 = lo32(w11);
                u32 al0 = hi32(w00), al1 = hi32(w10), al2 = hi32(w01), al3 = hi32(w11);
                #pragma unroll
                for (int nt = 0; nt < 4; nt++) {
                    const int nrow = wh * 32 + nt * 8 + rr4;
                    const int bi = nrow * BPITCH + q;
                    u64 bp0 = Bp[bi], bp1 = Bp[bi + 4];
                    float* d = acc + nt * 4;
                    mma16(d, ah0, ah1, ah2, ah3, lo32(bp0), lo32(bp1));
                    mma16(d, ah0, ah1, ah2, ah3, hi32(bp0), hi32(bp1));
                    mma16(d, al0, al1, al2, al3, lo32(bp0), lo32(bp1));
                }
            }
        }
        __syncthreads();   // all feature reads done

        // ---- bias + relu -> split h1 packed into A kpairs 0..31 ----
        {
            const int r = wm * 16 + rr4;
            #pragma unroll
            for (int nt = 0; nt < 4; nt++) {
                const int c = wh * 32 + nt * 8 + ka * 2;
                const int qh = c >> 1;                 // kpair index
                const float bb0 = b1s[c], bb1 = b1s[c + 1];
                float v0 = fmaxf(acc[nt * 4 + 0] + bb0, 0.f);
                float v1 = fmaxf(acc[nt * 4 + 1] + bb1, 0.f);
                Ap[r * AP + qh] = split_pack(v0, v1);
                float v2 = fmaxf(acc[nt * 4 + 2] + bb0, 0.f);
                float v3 = fmaxf(acc[nt * 4 + 3] + bb1, 0.f);
                Ap[(r + 8) * AP + qh] = split_pack(v2, v3);
            }
        }
        __syncthreads();   // h1 visible

        // ---- layer 2 (MMA, no splits) + layer 3 ----
        {
            float a2c[4] = {0.f, 0.f, 0.f, 0.f};
            const int r = wm2 * 16 + rr4;
            const u64* Ar0 = Ap + r * AP;
            const u64* Ar1 = Ap + (r + 8) * AP;
            #pragma unroll
            for (int ks = 0; ks < 4; ks++) {
                const int q = ks * 8 + ka;
                u64 w00 = Ar0[q], w01 = Ar0[q + 4];
                u64 w10 = Ar1[q], w11 = Ar1[q + 4];
                const int nrow = wnt * 8 + rr4;
                const int bi = nrow * W2PITCH + q;
                u64 bp0 = W2p[bi], bp1 = W2p[bi + 4];
                mma16(a2c, lo32(w00), lo32(w10), lo32(w01), lo32(w11), lo32(bp0), lo32(bp1));
                mma16(a2c, lo32(w00), lo32(w10), lo32(w01), lo32(w11), hi32(bp0), hi32(bp1));
                mma16(a2c, hi32(w00), hi32(w10), hi32(w01), hi32(w11), lo32(bp0), lo32(bp1));
            }
            const int j0 = wnt * 8 + ka * 2;
            const float w30 = w3s[j0], w31 = w3s[j0 + 1];
            const float bb0 = b2s[j0], bb1 = b2s[j0 + 1];
            float pr  = fmaxf(a2c[0] + bb0, 0.f) * w30 + fmaxf(a2c[1] + bb1, 0.f) * w31;
            float pr8 = fmaxf(a2c[2] + bb0, 0.f) * w30 + fmaxf(a2c[3] + bb1, 0.f) * w31;
            pr  += __shfl_xor_sync(0xffffffffu, pr, 1);
            pr  += __shfl_xor_sync(0xffffffffu, pr, 2);
            pr8 += __shfl_xor_sync(0xffffffffu, pr8, 1);
            pr8 += __shfl_xor_sync(0xffffffffu, pr8, 2);
            if (ka == 0) {
                s_pt[r * 2 + wnt]       = pr;
                s_pt[(r + 8) * 2 + wnt] = pr8;
            }
        }
        __syncthreads();

        // ---- combine + mask + atomic accumulate ----
        if (tid < NA && tid < nvalid) {
            float v = s_pt[tid * 2] + s_pt[tid * 2 + 1];
            float val = (v + s_ms[0]) * s_mk[tid];
            atomicAdd(&out[s_at[tid] >> 6], val);
        }
    }
}

// ---------------- launch -----------------------------------------------------
extern "C" void kernel_launch(void* const* d_in, const int* in_sizes, int n_in,
                              void* d_out, int out_size) {
    const float* x    = (const float*)d_in[0];
    const float* mask = (const float*)d_in[1];
    const float* W1   = (const float*)d_in[2];
    const float* b1   = (const float*)d_in[3];
    const float* W2   = (const float*)d_in[4];
    const float* b2   = (const float*)d_in[5];
    const float* W3   = (const float*)d_in[6];
    const float* b3   = (const float*)d_in[7];
    float* out = (float*)d_out;

    static void* cnt_addr = nullptr;
    static int   init_done = 0;
    if (!init_done) {
        cudaGetSymbolAddress(&cnt_addr, d_cnt);
        cudaFuncSetAttribute(mol_kernel, cudaFuncAttributeMaxDynamicSharedMemorySize,
                             SMEM_TOTAL);
        init_done = 1;
    }

    cudaMemsetAsync(cnt_addr, 0, NTYPE * sizeof(int));
    setup_kernel<<<CLS_BLOCKS + NTYPE, 256>>>(x, W1, b1, W2, b2, W3, b3, out);

    dim3 grid(NSLOT, NTYPE);
    mol_kernel<<<grid, NTHREADS, SMEM_TOTAL>>>(x, mask, b1, b2, W3, b3, out);
}

// round 11
// speedup vs baseline: 5.4909x; 1.0016x over previous
#include <cuda_runtime.h>
#include <cuda_bf16.h>

typedef unsigned int       u32;
typedef unsigned long long u64;

#define BATCH    4096
#define ATOMS    64
#define NATOMS   (BATCH * ATOMS)
#define FDIM     124
#define XROW     125
#define NTYPE    8
#define H1       64
#define H2       16
#define NA       128                 // atoms per chunk
#define NTHREADS 256
#define LISTCAP  40960
#define NSLOT    37                  // 37*8 = 296 CTAs = 148 SMs x 2

#define AP       68                  // u64 per A row (136 floats == 8 mod 32)
#define BPITCH   68                  // u64 per B row
#define W2PITCH  36                  // u64 per W2 row

// ---------------- SMEM layout (byte offsets) ---------------------------------
#define OFF_BP    0                          // Bp  u64[64][68]  = 34816
#define OFF_W2P   34816                      // W2p u64[16][36]  = 4608
#define OFF_A     39424                      // A   u64[128][68] = 69632
#define OFF_B1    109056                     // 256
#define OFF_B2    109312                     // 64
#define OFF_W3    109376                     // 64
#define OFF_MASK  109440                     // 512
#define OFF_ATOM  109952                     // 512
#define OFF_PART  110464                     // 512
#define OFF_MISC  110976                     // 16
#define SMEM_TOTAL 110992                    // -> 2 CTAs/SM

// ---------------- device globals ---------------------------------------------
__device__ float d_c[NTYPE];               // c_t = MLP_t(0)
__device__ int   d_cnt[NTYPE];
__device__ int   d_list[NTYPE][LISTCAP];
__device__ u64   d_w1p[NTYPE][H1 * 64];    // [t][n][kpair] (lo<<32)|hi
__device__ u64   d_w2p[NTYPE][H2 * 32];    // [t][j][hpair]

// ---------------- helpers ----------------------------------------------------
__device__ __forceinline__ u32 cvt2bf(float hi_elem, float lo_elem) {
    u32 r;
    asm("cvt.rn.bf16x2.f32 %0, %1, %2;" : "=r"(r) : "f"(hi_elem), "f"(lo_elem));
    return r;
}
__device__ __forceinline__ u64 split_pack(float fx, float fy) {
    u32 hi = cvt2bf(fy, fx);
    float ha = __uint_as_float(hi << 16);
    float hb = __uint_as_float(hi & 0xFFFF0000u);
    u32 lo = cvt2bf(fy - hb, fx - ha);
    return ((u64)lo << 32) | hi;
}
__device__ __forceinline__ void mma16(float* d, u32 a0, u32 a1, u32 a2, u32 a3,
                                      u32 b0, u32 b1) {
    asm volatile(
        "mma.sync.aligned.m16n8k16.row.col.f32.bf16.bf16.f32 "
        "{%0,%1,%2,%3}, {%4,%5,%6,%7}, {%8,%9}, {%0,%1,%2,%3};"
        : "+f"(d[0]), "+f"(d[1]), "+f"(d[2]), "+f"(d[3])
        : "r"(a0), "r"(a1), "r"(a2), "r"(a3), "r"(b0), "r"(b1));
}
__device__ __forceinline__ u32 lo32(u64 v) { return (u32)v; }
__device__ __forceinline__ u32 hi32(u64 v) { return (u32)(v >> 32); }

// ---------------- kernel 0: fused setup (classify + weight prep) -------------
#define CLS_ATOMS 1024
#define CLS_BLOCKS (NATOMS / CLS_ATOMS)     // 256
__global__ __launch_bounds__(256)
void setup_kernel(const float* __restrict__ x,
                  const float* __restrict__ W1,
                  const float* __restrict__ b1,
                  const float* __restrict__ W2,
                  const float* __restrict__ b2,
                  const float* __restrict__ W3,
                  const float* __restrict__ b3,
                  float* __restrict__ out) {
    const int tid = threadIdx.x;
    if (blockIdx.x < CLS_BLOCKS) {
        __shared__ int s_cnt[NTYPE];
        __shared__ int s_base[NTYPE];
        if (tid < NTYPE) s_cnt[tid] = 0;
        __syncthreads();
        const int a0 = blockIdx.x * CLS_ATOMS + tid * 4;
        int ty[4], rk[4];
        float tf0 = x[(size_t)(a0 + 0) * XROW];
        float tf1 = x[(size_t)(a0 + 1) * XROW];
        float tf2 = x[(size_t)(a0 + 2) * XROW];
        float tf3 = x[(size_t)(a0 + 3) * XROW];
        ty[0] = (int)tf0; ty[1] = (int)tf1; ty[2] = (int)tf2; ty[3] = (int)tf3;
        #pragma unroll
        for (int i = 0; i < 4; i++) rk[i] = atomicAdd(&s_cnt[ty[i]], 1);
        __syncthreads();
        if (tid < NTYPE) s_base[tid] = atomicAdd(&d_cnt[tid], s_cnt[tid]);
        __syncthreads();
        #pragma unroll
        for (int i = 0; i < 4; i++)
            d_list[ty[i]][s_base[ty[i]] + rk[i]] = a0 + i;
    } else {
        const int t = blockIdx.x - CLS_BLOCKS;
        for (int i = tid; i < H1 * 64; i += 256) {
            int n = i >> 6, p = i & 63;
            u64 w = 0;
            if (p < FDIM / 2) {
                float va = W1[(size_t)t * FDIM * H1 + (2 * p) * H1 + n];
                float vb = W1[(size_t)t * FDIM * H1 + (2 * p + 1) * H1 + n];
                w = split_pack(va, vb);
            }
            d_w1p[t][i] = w;
        }
        for (int i = tid; i < H2 * 32; i += 256) {
            int j = i >> 5, p = i & 31;
            float va = W2[(size_t)t * H1 * H2 + (2 * p) * H2 + j];
            float vb = W2[(size_t)t * H1 * H2 + (2 * p + 1) * H2 + j];
            d_w2p[t][i] = split_pack(va, vb);
        }
        for (int i = tid; i < BATCH / NTYPE; i += 256)
            out[t * (BATCH / NTYPE) + i] = 0.f;
        if (tid < 16) {
            const int g = tid;
            float v = b2[t * H2 + g];
            for (int h = 0; h < H1; h++)
                v += fmaxf(b1[t * H1 + h], 0.f) * W2[t * H1 * H2 + h * H2 + g];
            float o = fmaxf(v, 0.f) * W3[t * H2 + g];
            #pragma unroll
            for (int off = 8; off > 0; off >>= 1)
                o += __shfl_xor_sync(0xffffu, o, off);
            if (g == 0) d_c[t] = o + b3[t];
        }
    }
}

// ---------------- kernel 1: persistent per-type split-bf16 MMA MLP -----------
__global__ __launch_bounds__(NTHREADS, 2)
void mol_kernel(const float* __restrict__ x,
                const float* __restrict__ mask,
                const float* __restrict__ b1,
                const float* __restrict__ b2,
                const float* __restrict__ W3,
                const float* __restrict__ b3,
                float* __restrict__ out) {
    extern __shared__ char smraw[];
    const int tid = threadIdx.x, wid = tid >> 5, lane = tid & 31;
    const int t = blockIdx.y;
    const int cnt = d_cnt[t];

    u64*   Bp   = (u64*)(smraw + OFF_BP);
    u64*   W2p  = (u64*)(smraw + OFF_W2P);
    u64*   Ap   = (u64*)(smraw + OFF_A);
    float* b1s  = (float*)(smraw + OFF_B1);
    float* b2s  = (float*)(smraw + OFF_B2);
    float* w3s  = (float*)(smraw + OFF_W3);
    float* s_mk = (float*)(smraw + OFF_MASK);
    int*   s_at = (int*)(smraw + OFF_ATOM);
    float* s_pt = (float*)(smraw + OFF_PART);
    float* s_ms = (float*)(smraw + OFF_MISC);

    // ---- stage per-type constants ONCE ----
    {
        const u64* w1 = d_w1p[t];
        for (int i = tid; i < H1 * 64; i += NTHREADS) {
            int n = i >> 6, p = i & 63;
            Bp[n * BPITCH + p] = w1[i];
        }
        const u64* w2 = d_w2p[t];
        for (int i = tid; i < H2 * 32; i += NTHREADS) {
            int j = i >> 5, p = i & 31;
            W2p[j * W2PITCH + p] = w2[i];
        }
        if (tid < H1) b1s[tid] = b1[t * H1 + tid];
        if (tid < H2) { b2s[tid] = b2[t * H2 + tid]; w3s[tid] = W3[t * H2 + tid]; }
        if (tid == 0) {
            float tot = 0.f;
            #pragma unroll
            for (int u = 0; u < NTYPE; u++) tot += d_c[u];
            s_ms[0] = b3[t] + (tot - d_c[t]);   // b3 + correction
        }
    }

    const int wmm = wid >> 1;         // layer-1 m-group (32 rows)
    const int wnn = wid & 1;          // layer-1 n-half  (32 cols)
    const int rr4 = lane >> 2;
    const int ka  = lane & 3;
    const int mb  = wmm * 32;

    // ---- persistent chunk loop ----
    for (int base = blockIdx.x * NA; base < cnt; base += NSLOT * NA) {
        const int nvalid = min(NA, cnt - base);
        __syncthreads();   // prior chunk fully consumed

        if (tid < NA) {
            int idx = min(base + tid, cnt - 1);
            int a = d_list[t][idx];
            s_at[tid] = a;
            s_mk[tid] = mask[a];
        }
        __syncthreads();

        // ---- gather + split (pair-stride: 8B lane stride) ----
        {
            #pragma unroll
            for (int rr = 0; rr < 16; rr += 2) {
                const int s0 = wid * 16 + rr;
                const float* r0 = x + (size_t)s_at[s0] * XROW + 1;
                const float* r1 = x + (size_t)s_at[s0 + 1] * XROW + 1;
                if (lane < 31) {
                    const int l2 = 2 * lane;
                    float a0 = r0[l2], a1 = r0[l2 + 1];
                    float a2 = r0[l2 + 62], a3 = r0[l2 + 63];
                    float c0 = r1[l2], c1 = r1[l2 + 1];
                    float c2 = r1[l2 + 62], c3 = r1[l2 + 63];
                    Ap[s0 * AP + lane]            = split_pack(a0, a1);
                    Ap[s0 * AP + lane + 31]       = split_pack(a2, a3);
                    Ap[(s0 + 1) * AP + lane]      = split_pack(c0, c1);
                    Ap[(s0 + 1) * AP + lane + 31] = split_pack(c2, c3);
                } else {
                    ulonglong2 z; z.x = 0ull; z.y = 0ull;
                    *(ulonglong2*)(Ap + s0 * AP + 62)       = z;
                    *(ulonglong2*)(Ap + (s0 + 1) * AP + 62) = z;
                }
            }
        }
        __syncthreads();

        // ---- layer 1: warp tile 32 rows x 32 cols, 3-pass split-bf16 ----
        float acc[2][16];
        #pragma unroll
        for (int m = 0; m < 2; m++)
            #pragma unroll
            for (int i = 0; i < 16; i++) acc[m][i] = 0.f;
        {
            #pragma unroll
            for (int ks = 0; ks < 8; ks++) {
                const int q = ks * 8 + ka;
                u64 af[2][4];
                #pragma unroll
                for (int mt = 0; mt < 2; mt++) {
                    const int r = mb + mt * 16 + rr4;
                    af[mt][0] = Ap[r * AP + q];
                    af[mt][1] = Ap[(r + 8) * AP + q];
                    af[mt][2] = Ap[r * AP + q + 4];
                    af[mt][3] = Ap[(r + 8) * AP + q + 4];
                }
                #pragma unroll
                for (int nt = 0; nt < 4; nt++) {
                    const int bi = (wnn * 32 + nt * 8 + rr4) * BPITCH + q;
                    u64 bp0 = Bp[bi], bp1 = Bp[bi + 4];
                    u32 bh0 = lo32(bp0), bh1 = lo32(bp1);
                    u32 bl0 = hi32(bp0), bl1 = hi32(bp1);
                    #pragma unroll
                    for (int mt = 0; mt < 2; mt++) {
                        float* d = acc[mt] + nt * 4;
                        u32 ah0 = lo32(af[mt][0]), ah1 = lo32(af[mt][1]);
                        u32 ah2 = lo32(af[mt][2]), ah3 = lo32(af[mt][3]);
                        u32 al0 = hi32(af[mt][0]), al1 = hi32(af[mt][1]);
                        u32 al2 = hi32(af[mt][2]), al3 = hi32(af[mt][3]);
                        mma16(d, ah0, ah1, ah2, ah3, bh0, bh1);
                        mma16(d, ah0, ah1, ah2, ah3, bl0, bl1);
                        mma16(d, al0, al1, al2, al3, bh0, bh1);
                    }
                }
            }
        }
        __syncthreads();   // all feature reads done

        // ---- bias + relu -> split h1 packed into A kpairs 0..31 ----
        {
            #pragma unroll
            for (int mt = 0; mt < 2; mt++) {
                const int r = mb + mt * 16 + rr4;
                #pragma unroll
                for (int nt = 0; nt < 4; nt++) {
                    const int c = wnn * 32 + nt * 8 + ka * 2;
                    const int qh = c >> 1;
                    const float bb0 = b1s[c], bb1 = b1s[c + 1];
                    float v0 = fmaxf(acc[mt][nt * 4 + 0] + bb0, 0.f);
                    float v1 = fmaxf(acc[mt][nt * 4 + 1] + bb1, 0.f);
                    Ap[r * AP + qh] = split_pack(v0, v1);
                    float v2 = fmaxf(acc[mt][nt * 4 + 2] + bb0, 0.f);
                    float v3 = fmaxf(acc[mt][nt * 4 + 3] + bb1, 0.f);
                    Ap[(r + 8) * AP + qh] = split_pack(v2, v3);
                }
            }
        }
        __syncthreads();   // h1 visible

        // ---- layer 2 (MMA) + layer 3: 8 warps x 16 rows, full H2 ----
        {
            float a2c[8];
            #pragma unroll
            for (int i = 0; i < 8; i++) a2c[i] = 0.f;
            const int r = wid * 16 + rr4;
            const u64* Ar0 = Ap + r * AP;
            const u64* Ar1 = Ap + (r + 8) * AP;
            #pragma unroll
            for (int ks = 0; ks < 4; ks++) {
                const int q = ks * 8 + ka;
                u64 w00 = Ar0[q], w01 = Ar0[q + 4];
                u64 w10 = Ar1[q], w11 = Ar1[q + 4];
                u32 ah0 = lo32(w00), ah1 = lo32(w10), ah2 = lo32(w01), ah3 = lo32(w11);
                u32 al0 = hi32(w00), al1 = hi32(w10), al2 = hi32(w01), al3 = hi32(w11);
                #pragma unroll
                for (int nt2 = 0; nt2 < 2; nt2++) {
                    const int bi = (nt2 * 8 + rr4) * W2PITCH + q;
                    u64 bp0 = W2p[bi], bp1 = W2p[bi + 4];
                    float* d = a2c + nt2 * 4;
                    mma16(d, ah0, ah1, ah2, ah3, lo32(bp0), lo32(bp1));
                    mma16(d, ah0, ah1, ah2, ah3, hi32(bp0), hi32(bp1));
                    mma16(d, al0, al1, al2, al3, lo32(bp0), lo32(bp1));
                }
            }
            float pr = 0.f, pr8 = 0.f;
            #pragma unroll
            for (int nt2 = 0; nt2 < 2; nt2++) {
                const int j0 = nt2 * 8 + ka * 2;
                const float w30 = w3s[j0], w31 = w3s[j0 + 1];
                const float bb0 = b2s[j0], bb1 = b2s[j0 + 1];
                pr  += fmaxf(a2c[nt2 * 4 + 0] + bb0, 0.f) * w30
                     + fmaxf(a2c[nt2 * 4 + 1] + bb1, 0.f) * w31;
                pr8 += fmaxf(a2c[nt2 * 4 + 2] + bb0, 0.f) * w30
                     + fmaxf(a2c[nt2 * 4 + 3] + bb1, 0.f) * w31;
            }
            pr  += __shfl_xor_sync(0xffffffffu, pr, 1);
            pr  += __shfl_xor_sync(0xffffffffu, pr, 2);
            pr8 += __shfl_xor_sync(0xffffffffu, pr8, 1);
            pr8 += __shfl_xor_sync(0xffffffffu, pr8, 2);
            if (ka == 0) {
                s_pt[r]     = pr;
                s_pt[r + 8] = pr8;
            }
        }
        __syncthreads();

        // ---- combine + mask + atomic accumulate ----
        if (tid < NA && tid < nvalid) {
            float val = (s_pt[tid] + s_ms[0]) * s_mk[tid];
            atomicAdd(&out[s_at[tid] >> 6], val);
        }
    }
}

// ---------------- launch -----------------------------------------------------
extern "C" void kernel_launch(void* const* d_in, const int* in_sizes, int n_in,
                              void* d_out, int out_size) {
    const float* x    = (const float*)d_in[0];
    const float* mask = (const float*)d_in[1];
    const float* W1   = (const float*)d_in[2];
    const float* b1   = (const float*)d_in[3];
    const float* W2   = (const float*)d_in[4];
    const float* b2   = (const float*)d_in[5];
    const float* W3   = (const float*)d_in[6];
    const float* b3   = (const float*)d_in[7];
    float* out = (float*)d_out;

    static void* cnt_addr = nullptr;
    static int   init_done = 0;
    if (!init_done) {
        cudaGetSymbolAddress(&cnt_addr, d_cnt);
        cudaFuncSetAttribute(mol_kernel, cudaFuncAttributeMaxDynamicSharedMemorySize,
                             SMEM_TOTAL);
        init_done = 1;
    }

    cudaMemsetAsync(cnt_addr, 0, NTYPE * sizeof(int));
    setup_kernel<<<CLS_BLOCKS + NTYPE, 256>>>(x, W1, b1, W2, b2, W3, b3, out);

    dim3 grid(NSLOT, NTYPE);
    mol_kernel<<<grid, NTHREADS, SMEM_TOTAL>>>(x, mask, b1, b2, W3, b3, out);
}

// round 12
// speedup vs baseline: 5.8843x; 1.0717x over previous
#include <cuda_runtime.h>
#include <cuda_bf16.h>

typedef unsigned int       u32;
typedef unsigned long long u64;

#define BATCH    4096
#define ATOMS    64
#define NATOMS   (BATCH * ATOMS)
#define FDIM     124
#define XROW     125
#define NTYPE    8
#define H1       64
#define H2       16
#define NA       128                 // atoms per chunk (16 per warp)
#define NTHREADS 256
#define LISTCAP  40960
#define NSLOT    37                  // 37*8 = 296 CTAs = 148 SMs x 2

#define AP       68                  // u64 per A row (136 floats == 8 mod 32)
#define BPITCH   68                  // u64 per B row
#define W2PITCH  36                  // u64 per W2 row

// ---------------- SMEM layout (byte offsets) ---------------------------------
#define OFF_BP    0                          // Bp  u64[64][68]  = 34816
#define OFF_W2P   34816                      // W2p u64[16][36]  = 4608
#define OFF_A     39424                      // A   u64[128][68] = 69632 (warp-private 16-row slabs)
#define OFF_B1    109056                     // 256
#define OFF_B2    109312                     // 64
#define OFF_W3    109376                     // 64
#define OFF_MISC  109440                     // 16
#define SMEM_TOTAL 109456                    // -> 2 CTAs/SM

// ---------------- device globals ---------------------------------------------
__device__ float d_c[NTYPE];               // c_t = MLP_t(0)
__device__ int   d_cnt[NTYPE];
__device__ int   d_list[NTYPE][LISTCAP];
__device__ u64   d_w1p[NTYPE][H1 * 64];    // [t][n][kpair] (lo<<32)|hi
__device__ u64   d_w2p[NTYPE][H2 * 32];    // [t][j][hpair]

// ---------------- helpers ----------------------------------------------------
__device__ __forceinline__ u32 cvt2bf(float hi_elem, float lo_elem) {
    u32 r;
    asm("cvt.rn.bf16x2.f32 %0, %1, %2;" : "=r"(r) : "f"(hi_elem), "f"(lo_elem));
    return r;
}
__device__ __forceinline__ u64 split_pack(float fx, float fy) {
    u32 hi = cvt2bf(fy, fx);
    float ha = __uint_as_float(hi << 16);
    float hb = __uint_as_float(hi & 0xFFFF0000u);
    u32 lo = cvt2bf(fy - hb, fx - ha);
    return ((u64)lo << 32) | hi;
}
__device__ __forceinline__ void mma16(float* d, u32 a0, u32 a1, u32 a2, u32 a3,
                                      u32 b0, u32 b1) {
    asm volatile(
        "mma.sync.aligned.m16n8k16.row.col.f32.bf16.bf16.f32 "
        "{%0,%1,%2,%3}, {%4,%5,%6,%7}, {%8,%9}, {%0,%1,%2,%3};"
        : "+f"(d[0]), "+f"(d[1]), "+f"(d[2]), "+f"(d[3])
        : "r"(a0), "r"(a1), "r"(a2), "r"(a3), "r"(b0), "r"(b1));
}
__device__ __forceinline__ u32 lo32(u64 v) { return (u32)v; }
__device__ __forceinline__ u32 hi32(u64 v) { return (u32)(v >> 32); }

// ---------------- kernel 0: fused setup (classify + weight prep) -------------
#define CLS_ATOMS 1024
#define CLS_BLOCKS (NATOMS / CLS_ATOMS)     // 256
__global__ __launch_bounds__(256)
void setup_kernel(const float* __restrict__ x,
                  const float* __restrict__ W1,
                  const float* __restrict__ b1,
                  const float* __restrict__ W2,
                  const float* __restrict__ b2,
                  const float* __restrict__ W3,
                  const float* __restrict__ b3,
                  float* __restrict__ out) {
    const int tid = threadIdx.x;
    if (blockIdx.x < CLS_BLOCKS) {
        __shared__ int s_cnt[NTYPE];
        __shared__ int s_base[NTYPE];
        if (tid < NTYPE) s_cnt[tid] = 0;
        __syncthreads();
        const int a0 = blockIdx.x * CLS_ATOMS + tid * 4;
        int ty[4], rk[4];
        float tf0 = x[(size_t)(a0 + 0) * XROW];
        float tf1 = x[(size_t)(a0 + 1) * XROW];
        float tf2 = x[(size_t)(a0 + 2) * XROW];
        float tf3 = x[(size_t)(a0 + 3) * XROW];
        ty[0] = (int)tf0; ty[1] = (int)tf1; ty[2] = (int)tf2; ty[3] = (int)tf3;
        #pragma unroll
        for (int i = 0; i < 4; i++) rk[i] = atomicAdd(&s_cnt[ty[i]], 1);
        __syncthreads();
        if (tid < NTYPE) s_base[tid] = atomicAdd(&d_cnt[tid], s_cnt[tid]);
        __syncthreads();
        #pragma unroll
        for (int i = 0; i < 4; i++)
            d_list[ty[i]][s_base[ty[i]] + rk[i]] = a0 + i;
    } else {
        const int t = blockIdx.x - CLS_BLOCKS;
        for (int i = tid; i < H1 * 64; i += 256) {
            int n = i >> 6, p = i & 63;
            u64 w = 0;
            if (p < FDIM / 2) {
                float va = W1[(size_t)t * FDIM * H1 + (2 * p) * H1 + n];
                float vb = W1[(size_t)t * FDIM * H1 + (2 * p + 1) * H1 + n];
                w = split_pack(va, vb);
            }
            d_w1p[t][i] = w;
        }
        for (int i = tid; i < H2 * 32; i += 256) {
            int j = i >> 5, p = i & 31;
            float va = W2[(size_t)t * H1 * H2 + (2 * p) * H2 + j];
            float vb = W2[(size_t)t * H1 * H2 + (2 * p + 1) * H2 + j];
            d_w2p[t][i] = split_pack(va, vb);
        }
        for (int i = tid; i < BATCH / NTYPE; i += 256)
            out[t * (BATCH / NTYPE) + i] = 0.f;
        if (tid < 16) {
            const int g = tid;
            float v = b2[t * H2 + g];
            for (int h = 0; h < H1; h++)
                v += fmaxf(b1[t * H1 + h], 0.f) * W2[t * H1 * H2 + h * H2 + g];
            float o = fmaxf(v, 0.f) * W3[t * H2 + g];
            #pragma unroll
            for (int off = 8; off > 0; off >>= 1)
                o += __shfl_xor_sync(0xffffu, o, off);
            if (g == 0) d_c[t] = o + b3[t];
        }
    }
}

// ---------------- kernel 1: warp-autonomous persistent MLP -------------------
__global__ __launch_bounds__(NTHREADS, 2)
void mol_kernel(const float* __restrict__ x,
                const float* __restrict__ mask,
                const float* __restrict__ b1,
                const float* __restrict__ b2,
                const float* __restrict__ W3,
                const float* __restrict__ b3,
                float* __restrict__ out) {
    extern __shared__ char smraw[];
    const int tid = threadIdx.x, wid = tid >> 5, lane = tid & 31;
    const int t = blockIdx.y;
    const int cnt = d_cnt[t];

    u64*   Bp   = (u64*)(smraw + OFF_BP);
    u64*   W2p  = (u64*)(smraw + OFF_W2P);
    u64*   Ap   = (u64*)(smraw + OFF_A);
    float* b1s  = (float*)(smraw + OFF_B1);
    float* b2s  = (float*)(smraw + OFF_B2);
    float* w3s  = (float*)(smraw + OFF_W3);
    float* s_ms = (float*)(smraw + OFF_MISC);

    // ---- stage read-only shared data ONCE (single barrier) ----
    {
        const u64* w1 = d_w1p[t];
        for (int i = tid; i < H1 * 64; i += NTHREADS) {
            int n = i >> 6, p = i & 63;
            Bp[n * BPITCH + p] = w1[i];
        }
        const u64* w2 = d_w2p[t];
        for (int i = tid; i < H2 * 32; i += NTHREADS) {
            int j = i >> 5, p = i & 31;
            W2p[j * W2PITCH + p] = w2[i];
        }
        if (tid < H1) b1s[tid] = b1[t * H1 + tid];
        if (tid < H2) { b2s[tid] = b2[t * H2 + tid]; w3s[tid] = W3[t * H2 + tid]; }
        if (tid == 0) {
            float tot = 0.f;
            #pragma unroll
            for (int u = 0; u < NTYPE; u++) tot += d_c[u];
            s_ms[0] = b3[t] + (tot - d_c[t]);   // b3 + correction
        }
    }
    __syncthreads();   // the ONLY block barrier

    const int rr4 = lane >> 2;
    const int ka  = lane & 3;
    const int wb  = wid * 16;               // this warp's private A rows
    u64* Aw = Ap + wb * AP;
    const float cst = s_ms[0];

    // zero own k-pad (kpairs 62,63 of 16 rows) once; never rewritten
    if (lane < 16) {
        Aw[lane * AP + 62] = 0ull;
        Aw[lane * AP + 63] = 0ull;
    }
    __syncwarp();

    // ---- persistent warp-autonomous chunk loop (no block barriers) ----
    for (int base = blockIdx.x * NA; base < cnt; base += NSLOT * NA) {
        const int slot0 = base + wb;

        // atom ids + masks in lanes 0..15
        int aid = 0; float mk = 0.f;
        if (lane < 16) {
            int ix = min(slot0 + lane, cnt - 1);
            aid = d_list[t][ix];
            mk  = mask[aid];
        }
        __syncwarp();

        // ---- gather + split into own 16 rows (pair-stride) ----
        #pragma unroll
        for (int rr = 0; rr < 16; rr += 2) {
            const int a0id = __shfl_sync(0xffffffffu, aid, rr);
            const int a1id = __shfl_sync(0xffffffffu, aid, rr + 1);
            const float* r0 = x + (size_t)a0id * XROW + 1;
            const float* r1 = x + (size_t)a1id * XROW + 1;
            if (lane < 31) {
                const int l2 = 2 * lane;
                float f0 = r0[l2],      f1 = r0[l2 + 1];
                float f2 = r0[l2 + 62], f3 = r0[l2 + 63];
                float g0 = r1[l2],      g1 = r1[l2 + 1];
                float g2 = r1[l2 + 62], g3 = r1[l2 + 63];
                Aw[rr * AP + lane]            = split_pack(f0, f1);
                Aw[rr * AP + lane + 31]       = split_pack(f2, f3);
                Aw[(rr + 1) * AP + lane]      = split_pack(g0, g1);
                Aw[(rr + 1) * AP + lane + 31] = split_pack(g2, g3);
            }
        }
        __syncwarp();

        // ---- layer 1: own 16 rows x all 64 cols, 3-pass split-bf16 ----
        float acc[32];
        #pragma unroll
        for (int i = 0; i < 32; i++) acc[i] = 0.f;
        {
            const u64* Ar0 = Aw + rr4 * AP;
            const u64* Ar1 = Aw + (rr4 + 8) * AP;
            #pragma unroll
            for (int ks = 0; ks < 8; ks++) {
                const int q = ks * 8 + ka;
                u64 w00 = Ar0[q], w01 = Ar0[q + 4];
                u64 w10 = Ar1[q], w11 = Ar1[q + 4];
                u32 ah0 = lo32(w00), ah1 = lo32(w10), ah2 = lo32(w01), ah3 = lo32(w11);
                u32 al0 = hi32(w00), al1 = hi32(w10), al2 = hi32(w01), al3 = hi32(w11);
                #pragma unroll
                for (int nt = 0; nt < 8; nt++) {
                    const int bi = (nt * 8 + rr4) * BPITCH + q;
                    u64 bp0 = Bp[bi], bp1 = Bp[bi + 4];
                    float* d = acc + nt * 4;
                    mma16(d, ah0, ah1, ah2, ah3, lo32(bp0), lo32(bp1));
                    mma16(d, ah0, ah1, ah2, ah3, hi32(bp0), hi32(bp1));
                    mma16(d, al0, al1, al2, al3, lo32(bp0), lo32(bp1));
                }
            }
        }
        __syncwarp();   // own-row feature reads complete before h1 overwrite

        // ---- bias + relu -> split h1 into own rows, kpairs 0..31 ----
        #pragma unroll
        for (int nt = 0; nt < 8; nt++) {
            const int c = nt * 8 + ka * 2;
            const int qh = nt * 4 + ka;
            const float bb0 = b1s[c], bb1 = b1s[c + 1];
            float v0 = fmaxf(acc[nt * 4 + 0] + bb0, 0.f);
            float v1 = fmaxf(acc[nt * 4 + 1] + bb1, 0.f);
            Aw[rr4 * AP + qh] = split_pack(v0, v1);
            float v2 = fmaxf(acc[nt * 4 + 2] + bb0, 0.f);
            float v3 = fmaxf(acc[nt * 4 + 3] + bb1, 0.f);
            Aw[(rr4 + 8) * AP + qh] = split_pack(v2, v3);
        }
        __syncwarp();

        // ---- layer 2 (MMA) + layer 3 on own 16 rows ----
        {
            float a2c[8];
            #pragma unroll
            for (int i = 0; i < 8; i++) a2c[i] = 0.f;
            const u64* Ar0 = Aw + rr4 * AP;
            const u64* Ar1 = Aw + (rr4 + 8) * AP;
            #pragma unroll
            for (int ks = 0; ks < 4; ks++) {
                const int q = ks * 8 + ka;
                u64 w00 = Ar0[q], w01 = Ar0[q + 4];
                u64 w10 = Ar1[q], w11 = Ar1[q + 4];
                u32 ah0 = lo32(w00), ah1 = lo32(w10), ah2 = lo32(w01), ah3 = lo32(w11);
                u32 al0 = hi32(w00), al1 = hi32(w10), al2 = hi32(w01), al3 = hi32(w11);
                #pragma unroll
                for (int nt2 = 0; nt2 < 2; nt2++) {
                    const int bi = (nt2 * 8 + rr4) * W2PITCH + q;
                    u64 bp0 = W2p[bi], bp1 = W2p[bi + 4];
                    float* d = a2c + nt2 * 4;
                    mma16(d, ah0, ah1, ah2, ah3, lo32(bp0), lo32(bp1));
                    mma16(d, ah0, ah1, ah2, ah3, hi32(bp0), hi32(bp1));
                    mma16(d, al0, al1, al2, al3, lo32(bp0), lo32(bp1));
                }
            }
            float pr = 0.f, pr8 = 0.f;
            #pragma unroll
            for (int nt2 = 0; nt2 < 2; nt2++) {
                const int j0 = nt2 * 8 + ka * 2;
                const float w30 = w3s[j0], w31 = w3s[j0 + 1];
                const float bb0 = b2s[j0], bb1 = b2s[j0 + 1];
                pr  += fmaxf(a2c[nt2 * 4 + 0] + bb0, 0.f) * w30
                     + fmaxf(a2c[nt2 * 4 + 1] + bb1, 0.f) * w31;
                pr8 += fmaxf(a2c[nt2 * 4 + 2] + bb0, 0.f) * w30
                     + fmaxf(a2c[nt2 * 4 + 3] + bb1, 0.f) * w31;
            }
            pr  += __shfl_xor_sync(0xffffffffu, pr, 1);
            pr  += __shfl_xor_sync(0xffffffffu, pr, 2);
            pr8 += __shfl_xor_sync(0xffffffffu, pr8, 1);
            pr8 += __shfl_xor_sync(0xffffffffu, pr8, 2);

            // fetch row atom/mask via shfl (ids live in lanes 0..15)
            const int a0id = __shfl_sync(0xffffffffu, aid, rr4);
            const int a8id = __shfl_sync(0xffffffffu, aid, rr4 + 8);
            const float m0 = __shfl_sync(0xffffffffu, mk, rr4);
            const float m8 = __shfl_sync(0xffffffffu, mk, rr4 + 8);
            if (ka == 0) {
                if (slot0 + rr4 < cnt)
                    atomicAdd(&out[a0id >> 6], (pr + cst) * m0);
                if (slot0 + 8 + rr4 < cnt)
                    atomicAdd(&out[a8id >> 6], (pr8 + cst) * m8);
            }
        }
        __syncwarp();   // epilogue reads of h1 done before next gather overwrites
    }
}

// ---------------- launch -----------------------------------------------------
extern "C" void kernel_launch(void* const* d_in, const int* in_sizes, int n_in,
                              void* d_out, int out_size) {
    const float* x    = (const float*)d_in[0];
    const float* mask = (const float*)d_in[1];
    const float* W1   = (const float*)d_in[2];
    const float* b1   = (const float*)d_in[3];
    const float* W2   = (const float*)d_in[4];
    const float* b2   = (const float*)d_in[5];
    const float* W3   = (const float*)d_in[6];
    const float* b3   = (const float*)d_in[7];
    float* out = (float*)d_out;

    static void* cnt_addr = nullptr;
    static int   init_done = 0;
    if (!init_done) {
        cudaGetSymbolAddress(&cnt_addr, d_cnt);
        cudaFuncSetAttribute(mol_kernel, cudaFuncAttributeMaxDynamicSharedMemorySize,
                             SMEM_TOTAL);
        init_done = 1;
    }

    cudaMemsetAsync(cnt_addr, 0, NTYPE * sizeof(int));
    setup_kernel<<<CLS_BLOCKS + NTYPE, 256>>>(x, W1, b1, W2, b2, W3, b3, out);

    dim3 grid(NSLOT, NTYPE);
    mol_kernel<<<grid, NTHREADS, SMEM_TOTAL>>>(x, mask, b1, b2, W3, b3, out);
}

// round 13
// speedup vs baseline: 6.0427x; 1.0269x over previous
#include <cuda_runtime.h>
#include <cuda_bf16.h>

typedef unsigned int       u32;
typedef unsigned long long u64;

#define BATCH    4096
#define ATOMS    64
#define NATOMS   (BATCH * ATOMS)
#define FDIM     124
#define XROW     125
#define NTYPE    8
#define H1       64
#define H2       16
#define NA       64                  // atoms per chunk (16 per warp-pair)
#define NTHREADS 256
#define LISTCAP  40960
#define NSLOT    55                  // 55*8 = 440 CTAs ~= 148 SMs x 3

#define AP       68                  // u64 per A row (136 floats == 8 mod 32)
#define BPITCH   68                  // u64 per B row
#define W2PITCH  36                  // u64 per W2 row

// ---------------- SMEM layout (byte offsets) ---------------------------------
#define OFF_BP    0                          // Bp  u64[64][68] = 34816
#define OFF_W2P   34816                      // W2p u64[16][36] = 4608
#define OFF_A     39424                      // A   u64[64][68] = 34816
#define OFF_B1    74240                      // 256
#define OFF_B2    74496                      // 64
#define OFF_W3    74560                      // 64
#define OFF_PT    74624                      // s_pt f32[64][2] = 512
#define OFF_MISC  75136                      // 16
#define SMEM_TOTAL 75152                     // -> 3 CTAs/SM

// ---------------- device globals ---------------------------------------------
__device__ float d_c[NTYPE];               // c_t = MLP_t(0)
__device__ int   d_cnt[NTYPE];
__device__ int   d_list[NTYPE][LISTCAP];
__device__ u64   d_w1p[NTYPE][H1 * 64];    // [t][n][kpair] (lo<<32)|hi
__device__ u64   d_w2p[NTYPE][H2 * 32];    // [t][j][hpair]

// ---------------- helpers ----------------------------------------------------
__device__ __forceinline__ u32 cvt2bf(float hi_elem, float lo_elem) {
    u32 r;
    asm("cvt.rn.bf16x2.f32 %0, %1, %2;" : "=r"(r) : "f"(hi_elem), "f"(lo_elem));
    return r;
}
__device__ __forceinline__ u64 split_pack(float fx, float fy) {
    u32 hi = cvt2bf(fy, fx);
    float ha = __uint_as_float(hi << 16);
    float hb = __uint_as_float(hi & 0xFFFF0000u);
    u32 lo = cvt2bf(fy - hb, fx - ha);
    return ((u64)lo << 32) | hi;
}
__device__ __forceinline__ void mma16(float* d, u32 a0, u32 a1, u32 a2, u32 a3,
                                      u32 b0, u32 b1) {
    asm volatile(
        "mma.sync.aligned.m16n8k16.row.col.f32.bf16.bf16.f32 "
        "{%0,%1,%2,%3}, {%4,%5,%6,%7}, {%8,%9}, {%0,%1,%2,%3};"
        : "+f"(d[0]), "+f"(d[1]), "+f"(d[2]), "+f"(d[3])
        : "r"(a0), "r"(a1), "r"(a2), "r"(a3), "r"(b0), "r"(b1));
}
__device__ __forceinline__ u32 lo32(u64 v) { return (u32)v; }
__device__ __forceinline__ u32 hi32(u64 v) { return (u32)(v >> 32); }
#define BARP(id) asm volatile("bar.sync %0, 64;" :: "r"(id) : "memory")

// ---------------- kernel 0: fused setup (classify + weight prep) -------------
#define CLS_ATOMS 1024
#define CLS_BLOCKS (NATOMS / CLS_ATOMS)     // 256
__global__ __launch_bounds__(256)
void setup_kernel(const float* __restrict__ x,
                  const float* __restrict__ W1,
                  const float* __restrict__ b1,
                  const float* __restrict__ W2,
                  const float* __restrict__ b2,
                  const float* __restrict__ W3,
                  const float* __restrict__ b3,
                  float* __restrict__ out) {
    const int tid = threadIdx.x;
    if (blockIdx.x < CLS_BLOCKS) {
        __shared__ int s_cnt[NTYPE];
        __shared__ int s_base[NTYPE];
        if (tid < NTYPE) s_cnt[tid] = 0;
        __syncthreads();
        const int a0 = blockIdx.x * CLS_ATOMS + tid * 4;
        int ty[4], rk[4];
        float tf0 = x[(size_t)(a0 + 0) * XROW];
        float tf1 = x[(size_t)(a0 + 1) * XROW];
        float tf2 = x[(size_t)(a0 + 2) * XROW];
        float tf3 = x[(size_t)(a0 + 3) * XROW];
        ty[0] = (int)tf0; ty[1] = (int)tf1; ty[2] = (int)tf2; ty[3] = (int)tf3;
        #pragma unroll
        for (int i = 0; i < 4; i++) rk[i] = atomicAdd(&s_cnt[ty[i]], 1);
        __syncthreads();
        if (tid < NTYPE) s_base[tid] = atomicAdd(&d_cnt[tid], s_cnt[tid]);
        __syncthreads();
        #pragma unroll
        for (int i = 0; i < 4; i++)
            d_list[ty[i]][s_base[ty[i]] + rk[i]] = a0 + i;
    } else {
        const int t = blockIdx.x - CLS_BLOCKS;
        for (int i = tid; i < H1 * 64; i += 256) {
            int n = i >> 6, p = i & 63;
            u64 w = 0;
            if (p < FDIM / 2) {
                float va = W1[(size_t)t * FDIM * H1 + (2 * p) * H1 + n];
                float vb = W1[(size_t)t * FDIM * H1 + (2 * p + 1) * H1 + n];
                w = split_pack(va, vb);
            }
            d_w1p[t][i] = w;
        }
        for (int i = tid; i < H2 * 32; i += 256) {
            int j = i >> 5, p = i & 31;
            float va = W2[(size_t)t * H1 * H2 + (2 * p) * H2 + j];
            float vb = W2[(size_t)t * H1 * H2 + (2 * p + 1) * H2 + j];
            d_w2p[t][i] = split_pack(va, vb);
        }
        for (int i = tid; i < BATCH / NTYPE; i += 256)
            out[t * (BATCH / NTYPE) + i] = 0.f;
        if (tid < 16) {
            const int g = tid;
            float v = b2[t * H2 + g];
            for (int h = 0; h < H1; h++)
                v += fmaxf(b1[t * H1 + h], 0.f) * W2[t * H1 * H2 + h * H2 + g];
            float o = fmaxf(v, 0.f) * W3[t * H2 + g];
            #pragma unroll
            for (int off = 8; off > 0; off >>= 1)
                o += __shfl_xor_sync(0xffffu, o, off);
            if (g == 0) d_c[t] = o + b3[t];
        }
    }
}

// ---------------- kernel 1: warp-pair persistent MLP, 3 CTAs/SM --------------
__global__ __launch_bounds__(NTHREADS, 3)
void mol_kernel(const float* __restrict__ x,
                const float* __restrict__ mask,
                const float* __restrict__ b1,
                const float* __restrict__ b2,
                const float* __restrict__ W3,
                const float* __restrict__ b3,
                float* __restrict__ out) {
    extern __shared__ char smraw[];
    const int tid = threadIdx.x, wid = tid >> 5, lane = tid & 31;
    const int t = blockIdx.y;
    const int cnt = d_cnt[t];

    u64*   Bp   = (u64*)(smraw + OFF_BP);
    u64*   W2p  = (u64*)(smraw + OFF_W2P);
    u64*   Ap   = (u64*)(smraw + OFF_A);
    float* b1s  = (float*)(smraw + OFF_B1);
    float* b2s  = (float*)(smraw + OFF_B2);
    float* w3s  = (float*)(smraw + OFF_W3);
    float* s_pt = (float*)(smraw + OFF_PT);
    float* s_ms = (float*)(smraw + OFF_MISC);

    // ---- stage read-only shared data ONCE ----
    {
        const u64* w1 = d_w1p[t];
        for (int i = tid; i < H1 * 64; i += NTHREADS) {
            int n = i >> 6, p = i & 63;
            Bp[n * BPITCH + p] = w1[i];
        }
        const u64* w2 = d_w2p[t];
        for (int i = tid; i < H2 * 32; i += NTHREADS) {
            int j = i >> 5, p = i & 31;
            W2p[j * W2PITCH + p] = w2[i];
        }
        if (tid < H1) b1s[tid] = b1[t * H1 + tid];
        if (tid < H2) { b2s[tid] = b2[t * H2 + tid]; w3s[tid] = W3[t * H2 + tid]; }
        if (tid == 0) {
            float tot = 0.f;
            #pragma unroll
            for (int u = 0; u < NTYPE; u++) tot += d_c[u];
            s_ms[0] = b3[t] + (tot - d_c[t]);   // b3 + correction
        }
        // zero all k-pads (kpairs 62,63, rows 0..63)
        if (tid < 128) {
            int r = tid >> 1, kp = 62 + (tid & 1);
            Ap[r * AP + kp] = 0ull;
        }
    }
    __syncthreads();   // the ONLY block barrier

    const int pair = wid >> 1;               // 0..3
    const int wp   = wid & 1;                // warp-in-pair
    const int bid5 = pair + 1;               // named barrier id 1..4
    const int rr4  = lane >> 2;
    const int ka   = lane & 3;
    u64* Aw = Ap + pair * 16 * AP;           // pair's 16-row slab
    const float cst = s_ms[0];

    // ---- persistent warp-pair chunk loop ----
    for (int base = blockIdx.x * NA; base < cnt; base += NSLOT * NA) {
        const int slot0 = base + pair * 16;

        // atom ids + masks for the pair's 16 atoms (lanes 0..15, both warps)
        int aid = 0; float mk = 0.f;
        if (lane < 16) {
            int ix = min(slot0 + lane, cnt - 1);
            aid = d_list[t][ix];
            mk  = mask[aid];
        }

        // ---- gather + split own 8 rows (pair-stride) ----
        #pragma unroll
        for (int rr = 0; rr < 8; rr += 2) {
            const int srow = wp * 8 + rr;
            const int a0id = __shfl_sync(0xffffffffu, aid, srow);
            const int a1id = __shfl_sync(0xffffffffu, aid, srow + 1);
            const float* r0 = x + (size_t)a0id * XROW + 1;
            const float* r1 = x + (size_t)a1id * XROW + 1;
            if (lane < 31) {
                const int l2 = 2 * lane;
                float f0 = r0[l2],      f1 = r0[l2 + 1];
                float f2 = r0[l2 + 62], f3 = r0[l2 + 63];
                float g0 = r1[l2],      g1 = r1[l2 + 1];
                float g2 = r1[l2 + 62], g3 = r1[l2 + 63];
                Aw[srow * AP + lane]            = split_pack(f0, f1);
                Aw[srow * AP + lane + 31]       = split_pack(f2, f3);
                Aw[(srow + 1) * AP + lane]      = split_pack(g0, g1);
                Aw[(srow + 1) * AP + lane + 31] = split_pack(g2, g3);
            }
        }
        BARP(bid5);   // pair's 16 rows complete

        // ---- layer 1: 16 rows x 32 cols (own n-half), 3-pass split-bf16 ----
        float acc[16];
        #pragma unroll
        for (int i = 0; i < 16; i++) acc[i] = 0.f;
        {
            const u64* Ar0 = Aw + rr4 * AP;
            const u64* Ar1 = Aw + (rr4 + 8) * AP;
            #pragma unroll
            for (int ks = 0; ks < 8; ks++) {
                const int q = ks * 8 + ka;
                u64 w00 = Ar0[q], w01 = Ar0[q + 4];
                u64 w10 = Ar1[q], w11 = Ar1[q + 4];
                u32 ah0 = lo32(w00), ah1 = lo32(w10), ah2 = lo32(w01), ah3 = lo32(w11);
                u32 al0 = hi32(w00), al1 = hi32(w10), al2 = hi32(w01), al3 = hi32(w11);
                #pragma unroll
                for (int nt = 0; nt < 4; nt++) {
                    const int bi = (wp * 32 + nt * 8 + rr4) * BPITCH + q;
                    u64 bp0 = Bp[bi], bp1 = Bp[bi + 4];
                    float* d = acc + nt * 4;
                    mma16(d, ah0, ah1, ah2, ah3, lo32(bp0), lo32(bp1));
                    mma16(d, ah0, ah1, ah2, ah3, hi32(bp0), hi32(bp1));
                    mma16(d, al0, al1, al2, al3, lo32(bp0), lo32(bp1));
                }
            }
        }
        BARP(bid5);   // both warps done reading features

        // ---- bias + relu -> split h1 into own cols (kpairs wp*16..wp*16+15) --
        #pragma unroll
        for (int nt = 0; nt < 4; nt++) {
            const int c = wp * 32 + nt * 8 + ka * 2;
            const int qh = wp * 16 + nt * 4 + ka;
            const float bb0 = b1s[c], bb1 = b1s[c + 1];
            float v0 = fmaxf(acc[nt * 4 + 0] + bb0, 0.f);
            float v1 = fmaxf(acc[nt * 4 + 1] + bb1, 0.f);
            Aw[rr4 * AP + qh] = split_pack(v0, v1);
            float v2 = fmaxf(acc[nt * 4 + 2] + bb0, 0.f);
            float v3 = fmaxf(acc[nt * 4 + 3] + bb1, 0.f);
            Aw[(rr4 + 8) * AP + qh] = split_pack(v2, v3);
        }
        BARP(bid5);   // h1 complete

        // ---- layer 2 (MMA, own j-half) + layer 3 partials ----
        {
            float a2c[4] = {0.f, 0.f, 0.f, 0.f};
            const u64* Ar0 = Aw + rr4 * AP;
            const u64* Ar1 = Aw + (rr4 + 8) * AP;
            #pragma unroll
            for (int ks = 0; ks < 4; ks++) {
                const int q = ks * 8 + ka;
                u64 w00 = Ar0[q], w01 = Ar0[q + 4];
                u64 w10 = Ar1[q], w11 = Ar1[q + 4];
                const int bi = (wp * 8 + rr4) * W2PITCH + q;
                u64 bp0 = W2p[bi], bp1 = W2p[bi + 4];
                mma16(a2c, lo32(w00), lo32(w10), lo32(w01), lo32(w11),
                      lo32(bp0), lo32(bp1));
                mma16(a2c, lo32(w00), lo32(w10), lo32(w01), lo32(w11),
                      hi32(bp0), hi32(bp1));
                mma16(a2c, hi32(w00), hi32(w10), hi32(w01), hi32(w11),
                      lo32(bp0), lo32(bp1));
            }
            const int j0 = wp * 8 + ka * 2;
            const float w30 = w3s[j0], w31 = w3s[j0 + 1];
            const float bb0 = b2s[j0], bb1 = b2s[j0 + 1];
            float pr  = fmaxf(a2c[0] + bb0, 0.f) * w30 + fmaxf(a2c[1] + bb1, 0.f) * w31;
            float pr8 = fmaxf(a2c[2] + bb0, 0.f) * w30 + fmaxf(a2c[3] + bb1, 0.f) * w31;
            pr  += __shfl_xor_sync(0xffffffffu, pr, 1);
            pr  += __shfl_xor_sync(0xffffffffu, pr, 2);
            pr8 += __shfl_xor_sync(0xffffffffu, pr8, 1);
            pr8 += __shfl_xor_sync(0xffffffffu, pr8, 2);
            if (ka == 0) {
                s_pt[(pair * 16 + rr4) * 2 + wp]     = pr;
                s_pt[(pair * 16 + rr4 + 8) * 2 + wp] = pr8;
            }
        }
        BARP(bid5);   // partials ready

        // ---- combine + mask + atomic accumulate (warp 0 of pair) ----
        if (wp == 0 && lane < 16) {
            if (slot0 + lane < cnt) {
                const int row = pair * 16 + lane;
                float v = s_pt[row * 2] + s_pt[row * 2 + 1];
                atomicAdd(&out[aid >> 6], (v + cst) * mk);
            }
        }
        // next iteration's first BARP orders slab/s_pt reuse
    }
}

// ---------------- launch -----------------------------------------------------
extern "C" void kernel_launch(void* const* d_in, const int* in_sizes, int n_in,
                              void* d_out, int out_size) {
    const float* x    = (const float*)d_in[0];
    const float* mask = (const float*)d_in[1];
    const float* W1   = (const float*)d_in[2];
    const float* b1   = (const float*)d_in[3];
    const float* W2   = (const float*)d_in[4];
    const float* b2   = (const float*)d_in[5];
    const float* W3   = (const float*)d_in[6];
    const float* b3   = (const float*)d_in[7];
    float* out = (float*)d_out;

    static void* cnt_addr = nullptr;
    static int   init_done = 0;
    if (!init_done) {
        cudaGetSymbolAddress(&cnt_addr, d_cnt);
        cudaFuncSetAttribute(mol_kernel, cudaFuncAttributeMaxDynamicSharedMemorySize,
                             SMEM_TOTAL);
        init_done = 1;
    }

    cudaMemsetAsync(cnt_addr, 0, NTYPE * sizeof(int));
    setup_kernel<<<CLS_BLOCKS + NTYPE, 256>>>(x, W1, b1, W2, b2, W3, b3, out);

    dim3 grid(NSLOT, NTYPE);
    mol_kernel<<<grid, NTHREADS, SMEM_TOTAL>>>(x, mask, b1, b2, W3, b3, out);
}

// round 14
// speedup vs baseline: 6.5710x; 1.0874x over previous
#include <cuda_runtime.h>
#include <cuda_bf16.h>

typedef unsigned int       u32;
typedef unsigned long long u64;

#define BATCH    4096
#define ATOMS    64
#define NATOMS   (BATCH * ATOMS)
#define FDIM     124
#define XROW     125
#define NTYPE    8
#define H1       64
#define H2       16
#define NA       64                  // atoms per chunk (16 per warp-pair)
#define NTHREADS 256
#define LISTCAP  40960
#define NSLOT    55                  // 55*8 = 440 CTAs ~= 148 SMs x 3

#define AP       68                  // u64 per A row (136 floats == 8 mod 32)
#define BPITCH   68                  // u64 per B row
#define W2PITCH  36                  // u64 per W2 row

// ---------------- SMEM layout (byte offsets) ---------------------------------
#define OFF_BP    0                          // Bp  u64[64][68] = 34816
#define OFF_W2P   34816                      // W2p u64[16][36] = 4608
#define OFF_A     39424                      // A   u64[64][68] = 34816
#define OFF_B1    74240                      // 256
#define OFF_B2    74496                      // 64
#define OFF_W3    74560                      // 64
#define OFF_PT    74624                      // s_pt f32[64][2] = 512
#define OFF_MISC  75136                      // 16
#define SMEM_TOTAL 75152                     // -> 3 CTAs/SM

// ---------------- device globals ---------------------------------------------
__device__ float d_c[NTYPE];               // c_t = MLP_t(0)
__device__ int   d_cnt[NTYPE];
__device__ int   d_list[NTYPE][LISTCAP];
__device__ u64   d_w1p[NTYPE][H1 * 64];    // [t][n][kpair] (lo<<32)|hi
__device__ u64   d_w2p[NTYPE][H2 * 32];    // [t][j][hpair]

// ---------------- helpers ----------------------------------------------------
__device__ __forceinline__ u32 cvt2bf(float hi_elem, float lo_elem) {
    u32 r;
    asm("cvt.rn.bf16x2.f32 %0, %1, %2;" : "=r"(r) : "f"(hi_elem), "f"(lo_elem));
    return r;
}
__device__ __forceinline__ u64 split_pack(float fx, float fy) {
    u32 hi = cvt2bf(fy, fx);
    float ha = __uint_as_float(hi << 16);
    float hb = __uint_as_float(hi & 0xFFFF0000u);
    u32 lo = cvt2bf(fy - hb, fx - ha);
    return ((u64)lo << 32) | hi;
}
__device__ __forceinline__ void mma16(float* d, u32 a0, u32 a1, u32 a2, u32 a3,
                                      u32 b0, u32 b1) {
    asm volatile(
        "mma.sync.aligned.m16n8k16.row.col.f32.bf16.bf16.f32 "
        "{%0,%1,%2,%3}, {%4,%5,%6,%7}, {%8,%9}, {%0,%1,%2,%3};"
        : "+f"(d[0]), "+f"(d[1]), "+f"(d[2]), "+f"(d[3])
        : "r"(a0), "r"(a1), "r"(a2), "r"(a3), "r"(b0), "r"(b1));
}
__device__ __forceinline__ u32 lo32(u64 v) { return (u32)v; }
__device__ __forceinline__ u32 hi32(u64 v) { return (u32)(v >> 32); }
#define BARP(id) asm volatile("bar.sync %0, 64;" :: "r"(id) : "memory")
#define PF_L2(p) asm volatile("prefetch.global.L2 [%0];" :: "l"(p))

// ---------------- kernel 0: fused setup (classify + weight prep) -------------
#define CLS_ATOMS 1024
#define CLS_BLOCKS (NATOMS / CLS_ATOMS)     // 256
__global__ __launch_bounds__(256)
void setup_kernel(const float* __restrict__ x,
                  const float* __restrict__ mask,
                  const float* __restrict__ W1,
                  const float* __restrict__ b1,
                  const float* __restrict__ W2,
                  const float* __restrict__ b2,
                  const float* __restrict__ W3,
                  const float* __restrict__ b3,
                  float* __restrict__ out) {
    const int tid = threadIdx.x;
    if (blockIdx.x < CLS_BLOCKS) {
        __shared__ int s_cnt[NTYPE];
        __shared__ int s_base[NTYPE];
        if (tid < NTYPE) s_cnt[tid] = 0;
        __syncthreads();
        const int a0 = blockIdx.x * CLS_ATOMS + tid * 4;
        int ty[4], rk[4];
        float mv[4];
        #pragma unroll
        for (int i = 0; i < 4; i++) {
            mv[i] = mask[a0 + i];
            ty[i] = (int)x[(size_t)(a0 + i) * XROW];
        }
        #pragma unroll
        for (int i = 0; i < 4; i++)
            rk[i] = (mv[i] != 0.f) ? atomicAdd(&s_cnt[ty[i]], 1) : -1;
        __syncthreads();
        if (tid < NTYPE) s_base[tid] = atomicAdd(&d_cnt[tid], s_cnt[tid]);
        __syncthreads();
        #pragma unroll
        for (int i = 0; i < 4; i++)
            if (rk[i] >= 0)
                d_list[ty[i]][s_base[ty[i]] + rk[i]] = a0 + i;
    } else {
        const int t = blockIdx.x - CLS_BLOCKS;
        for (int i = tid; i < H1 * 64; i += 256) {
            int n = i >> 6, p = i & 63;
            u64 w = 0;
            if (p < FDIM / 2) {
                float va = W1[(size_t)t * FDIM * H1 + (2 * p) * H1 + n];
                float vb = W1[(size_t)t * FDIM * H1 + (2 * p + 1) * H1 + n];
                w = split_pack(va, vb);
            }
            d_w1p[t][i] = w;
        }
        for (int i = tid; i < H2 * 32; i += 256) {
            int j = i >> 5, p = i & 31;
            float va = W2[(size_t)t * H1 * H2 + (2 * p) * H2 + j];
            float vb = W2[(size_t)t * H1 * H2 + (2 * p + 1) * H2 + j];
            d_w2p[t][i] = split_pack(va, vb);
        }
        for (int i = tid; i < BATCH / NTYPE; i += 256)
            out[t * (BATCH / NTYPE) + i] = 0.f;
        if (tid < 16) {
            const int g = tid;
            float v = b2[t * H2 + g];
            for (int h = 0; h < H1; h++)
                v += fmaxf(b1[t * H1 + h], 0.f) * W2[t * H1 * H2 + h * H2 + g];
            float o = fmaxf(v, 0.f) * W3[t * H2 + g];
            #pragma unroll
            for (int off = 8; off > 0; off >>= 1)
                o += __shfl_xor_sync(0xffffu, o, off);
            if (g == 0) d_c[t] = o + b3[t];
        }
    }
}

// ---------------- kernel 1: warp-pair persistent MLP + L2 prefetch -----------
__global__ __launch_bounds__(NTHREADS, 3)
void mol_kernel(const float* __restrict__ x,
                const float* __restrict__ b1,
                const float* __restrict__ b2,
                const float* __restrict__ W3,
                const float* __restrict__ b3,
                float* __restrict__ out) {
    extern __shared__ char smraw[];
    const int tid = threadIdx.x, wid = tid >> 5, lane = tid & 31;
    const int t = blockIdx.y;
    const int cnt = d_cnt[t];

    u64*   Bp   = (u64*)(smraw + OFF_BP);
    u64*   W2p  = (u64*)(smraw + OFF_W2P);
    u64*   Ap   = (u64*)(smraw + OFF_A);
    float* b1s  = (float*)(smraw + OFF_B1);
    float* b2s  = (float*)(smraw + OFF_B2);
    float* w3s  = (float*)(smraw + OFF_W3);
    float* s_pt = (float*)(smraw + OFF_PT);
    float* s_ms = (float*)(smraw + OFF_MISC);

    // ---- stage read-only shared data ONCE ----
    {
        const u64* w1 = d_w1p[t];
        for (int i = tid; i < H1 * 64; i += NTHREADS) {
            int n = i >> 6, p = i & 63;
            Bp[n * BPITCH + p] = w1[i];
        }
        const u64* w2 = d_w2p[t];
        for (int i = tid; i < H2 * 32; i += NTHREADS) {
            int j = i >> 5, p = i & 31;
            W2p[j * W2PITCH + p] = w2[i];
        }
        if (tid < H1) b1s[tid] = b1[t * H1 + tid];
        if (tid < H2) { b2s[tid] = b2[t * H2 + tid]; w3s[tid] = W3[t * H2 + tid]; }
        if (tid == 0) {
            float tot = 0.f;
            #pragma unroll
            for (int u = 0; u < NTYPE; u++) tot += d_c[u];
            s_ms[0] = b3[t] + (tot - d_c[t]);   // b3 + correction
        }
        if (tid < 128) {
            int r = tid >> 1, kp = 62 + (tid & 1);
            Ap[r * AP + kp] = 0ull;
        }
    }
    __syncthreads();   // the ONLY block barrier

    const int pair = wid >> 1;               // 0..3
    const int wp   = wid & 1;                // warp-in-pair
    const int bid5 = pair + 1;               // named barrier id 1..4
    const int rr4  = lane >> 2;
    const int ka   = lane & 3;
    u64* Aw = Ap + pair * 16 * AP;           // pair's 16-row slab
    const float cst = s_ms[0];

    // ---- persistent warp-pair chunk loop ----
    for (int base = blockIdx.x * NA; base < cnt; base += NSLOT * NA) {
        const int slot0 = base + pair * 16;

        // atom ids for the pair's 16 atoms (lanes 0..15, both warps)
        int aid = 0;
        if (lane < 16) {
            int ix = min(slot0 + lane, cnt - 1);
            aid = d_list[t][ix];
        }

        // ---- gather + split own 8 rows (pair-stride) ----
        #pragma unroll
        for (int rr = 0; rr < 8; rr += 2) {
            const int srow = wp * 8 + rr;
            const int a0id = __shfl_sync(0xffffffffu, aid, srow);
            const int a1id = __shfl_sync(0xffffffffu, aid, srow + 1);
            const float* r0 = x + (size_t)a0id * XROW + 1;
            const float* r1 = x + (size_t)a1id * XROW + 1;
            if (lane < 31) {
                const int l2 = 2 * lane;
                float f0 = r0[l2],      f1 = r0[l2 + 1];
                float f2 = r0[l2 + 62], f3 = r0[l2 + 63];
                float g0 = r1[l2],      g1 = r1[l2 + 1];
                float g2 = r1[l2 + 62], g3 = r1[l2 + 63];
                Aw[srow * AP + lane]            = split_pack(f0, f1);
                Aw[srow * AP + lane + 31]       = split_pack(f2, f3);
                Aw[(srow + 1) * AP + lane]      = split_pack(g0, g1);
                Aw[(srow + 1) * AP + lane + 31] = split_pack(g2, g3);
            }
        }

        // ---- prefetch NEXT chunk's feature rows into L2 ----
        {
            const int nbase = base + NSLOT * NA;
            if (nbase < cnt) {
                const int r   = lane >> 2;            // 8 rows per warp
                const int seg = lane & 3;             // 4 x 128B segments
                int nix = min(nbase + pair * 16 + wp * 8 + r, cnt - 1);
                int na = d_list[t][nix];
                const char* p = (const char*)(x + (size_t)na * XROW + 1) + seg * 128;
                PF_L2(p);
            }
        }
        BARP(bid5);   // pair's 16 rows complete

        // ---- layer 1: 16 rows x 32 cols (own n-half), 3-pass split-bf16 ----
        float acc[16];
        #pragma unroll
        for (int i = 0; i < 16; i++) acc[i] = 0.f;
        {
            const u64* Ar0 = Aw + rr4 * AP;
            const u64* Ar1 = Aw + (rr4 + 8) * AP;
            #pragma unroll
            for (int ks = 0; ks < 8; ks++) {
                const int q = ks * 8 + ka;
                u64 w00 = Ar0[q], w01 = Ar0[q + 4];
                u64 w10 = Ar1[q], w11 = Ar1[q + 4];
                u32 ah0 = lo32(w00), ah1 = lo32(w10), ah2 = lo32(w01), ah3 = lo32(w11);
                u32 al0 = hi32(w00), al1 = hi32(w10), al2 = hi32(w01), al3 = hi32(w11);
                #pragma unroll
                for (int nt = 0; nt < 4; nt++) {
                    const int bi = (wp * 32 + nt * 8 + rr4) * BPITCH + q;
                    u64 bp0 = Bp[bi], bp1 = Bp[bi + 4];
                    float* d = acc + nt * 4;
                    mma16(d, ah0, ah1, ah2, ah3, lo32(bp0), lo32(bp1));
                    mma16(d, ah0, ah1, ah2, ah3, hi32(bp0), hi32(bp1));
                    mma16(d, al0, al1, al2, al3, lo32(bp0), lo32(bp1));
                }
            }
        }
        BARP(bid5);   // both warps done reading features

        // ---- bias + relu -> split h1 into own cols (kpairs wp*16..wp*16+15) --
        #pragma unroll
        for (int nt = 0; nt < 4; nt++) {
            const int c = wp * 32 + nt * 8 + ka * 2;
            const int qh = wp * 16 + nt * 4 + ka;
            const float bb0 = b1s[c], bb1 = b1s[c + 1];
            float v0 = fmaxf(acc[nt * 4 + 0] + bb0, 0.f);
            float v1 = fmaxf(acc[nt * 4 + 1] + bb1, 0.f);
            Aw[rr4 * AP + qh] = split_pack(v0, v1);
            float v2 = fmaxf(acc[nt * 4 + 2] + bb0, 0.f);
            float v3 = fmaxf(acc[nt * 4 + 3] + bb1, 0.f);
            Aw[(rr4 + 8) * AP + qh] = split_pack(v2, v3);
        }
        BARP(bid5);   // h1 complete

        // ---- layer 2 (MMA, own j-half) + layer 3 partials ----
        {
            float a2c[4] = {0.f, 0.f, 0.f, 0.f};
            const u64* Ar0 = Aw + rr4 * AP;
            const u64* Ar1 = Aw + (rr4 + 8) * AP;
            #pragma unroll
            for (int ks = 0; ks < 4; ks++) {
                const int q = ks * 8 + ka;
                u64 w00 = Ar0[q], w01 = Ar0[q + 4];
                u64 w10 = Ar1[q], w11 = Ar1[q + 4];
                const int bi = (wp * 8 + rr4) * W2PITCH + q;
                u64 bp0 = W2p[bi], bp1 = W2p[bi + 4];
                mma16(a2c, lo32(w00), lo32(w10), lo32(w01), lo32(w11),
                      lo32(bp0), lo32(bp1));
                mma16(a2c, lo32(w00), lo32(w10), lo32(w01), lo32(w11),
                      hi32(bp0), hi32(bp1));
                mma16(a2c, hi32(w00), hi32(w10), hi32(w01), hi32(w11),
                      lo32(bp0), lo32(bp1));
            }
            const int j0 = wp * 8 + ka * 2;
            const float w30 = w3s[j0], w31 = w3s[j0 + 1];
            const float bb0 = b2s[j0], bb1 = b2s[j0 + 1];
            float pr  = fmaxf(a2c[0] + bb0, 0.f) * w30 + fmaxf(a2c[1] + bb1, 0.f) * w31;
            float pr8 = fmaxf(a2c[2] + bb0, 0.f) * w30 + fmaxf(a2c[3] + bb1, 0.f) * w31;
            pr  += __shfl_xor_sync(0xffffffffu, pr, 1);
            pr  += __shfl_xor_sync(0xffffffffu, pr, 2);
            pr8 += __shfl_xor_sync(0xffffffffu, pr8, 1);
            pr8 += __shfl_xor_sync(0xffffffffu, pr8, 2);
            if (ka == 0) {
                s_pt[(pair * 16 + rr4) * 2 + wp]     = pr;
                s_pt[(pair * 16 + rr4 + 8) * 2 + wp] = pr8;
            }
        }
        BARP(bid5);   // partials ready

        // ---- combine + atomic accumulate (mask==1 for all listed atoms) ----
        if (wp == 0 && lane < 16) {
            if (slot0 + lane < cnt) {
                const int row = pair * 16 + lane;
                float v = s_pt[row * 2] + s_pt[row * 2 + 1];
                atomicAdd(&out[aid >> 6], v + cst);
            }
        }
        // next iteration's first BARP orders slab/s_pt reuse
    }
}

// ---------------- launch -----------------------------------------------------
extern "C" void kernel_launch(void* const* d_in, const int* in_sizes, int n_in,
                              void* d_out, int out_size) {
    const float* x    = (const float*)d_in[0];
    const float* mask = (const float*)d_in[1];
    const float* W1   = (const float*)d_in[2];
    const float* b1   = (const float*)d_in[3];
    const float* W2   = (const float*)d_in[4];
    const float* b2   = (const float*)d_in[5];
    const float* W3   = (const float*)d_in[6];
    const float* b3   = (const float*)d_in[7];
    float* out = (float*)d_out;

    static void* cnt_addr = nullptr;
    static int   init_done = 0;
    if (!init_done) {
        cudaGetSymbolAddress(&cnt_addr, d_cnt);
        cudaFuncSetAttribute(mol_kernel, cudaFuncAttributeMaxDynamicSharedMemorySize,
                             SMEM_TOTAL);
        init_done = 1;
    }

    cudaMemsetAsync(cnt_addr, 0, NTYPE * sizeof(int));
    setup_kernel<<<CLS_BLOCKS + NTYPE, 256>>>(x, mask, W1, b1, W2, b2, W3, b3, out);

    dim3 grid(NSLOT, NTYPE);
    mol_kernel<<<grid, NTHREADS, SMEM_TOTAL>>>(x, b1, b2, W3, b3, out);
}